// round 1
// baseline (speedup 1.0000x reference)
#include <cuda_runtime.h>
#include <cuda_bf16.h>

// Problem constants
#define BATCH 4
#define C_IN 256
#define C_MID 128
#define NSP 4096            // 64*64 spatial
#define INVN (1.0f/4096.0f)

// ---------------------------------------------------------------------------
// Device scratch (no allocations allowed)
// ---------------------------------------------------------------------------
__device__ __align__(256) float d_G[BATCH * C_IN * C_IN];    // Gram X X^T per batch
__device__ __align__(256) float d_s[BATCH * C_IN];           // row sums X*1
__device__ __align__(256) float d_U[BATCH * C_IN * C_IN];    // OG @ G
__device__ __align__(256) float d_Afold[BATCH * C_IN * C_IN];// folded operator A_b
__device__ __align__(256) float d_OG[C_IN * C_IN];           // out_w @ g_w
__device__ __align__(256) float d_PT[C_IN * C_IN];           // phi_w^T @ theta_w
__device__ __align__(256) float d_phiT[C_IN * C_MID];        // phi_w^T
__device__ __align__(256) float d_og[C_IN];                  // out_w @ g_b
__device__ __align__(256) float d_tp[C_IN];                  // theta_w^T @ phi_b
__device__ __align__(256) float d_q[C_IN];                   // phi_w^T @ theta_b
__device__ __align__(256) float d_up[BATCH * C_IN];          // (OG @ s)/N
__device__ __align__(256) float d_vp[BATCH * C_IN];          // v/N + tp
__device__ __align__(256) float d_cvec[BATCH * C_IN];        // per-batch bias c
__device__ float d_alpha;                                    // phi_b . theta_b

// ---------------------------------------------------------------------------
// Helpers
// ---------------------------------------------------------------------------
__device__ __forceinline__ float warp_dot(const float* __restrict__ row,
                                          const float* __restrict__ v, int K) {
    int lane = threadIdx.x & 31;
    float a = 0.f;
    for (int k = lane; k < K; k += 32) a += row[k] * v[k];
#pragma unroll
    for (int o = 16; o; o >>= 1) a += __shfl_xor_sync(0xffffffffu, a, o);
    return a;
}

// ---------------------------------------------------------------------------
// Zero scratch accumulators (G, s)
// ---------------------------------------------------------------------------
__global__ void zero_kernel() {
    int idx = blockIdx.x * blockDim.x + threadIdx.x;
    if (idx < BATCH * C_IN * C_IN) d_G[idx] = 0.f;
    if (idx < BATCH * C_IN)        d_s[idx] = 0.f;
}

// ---------------------------------------------------------------------------
// Transpose phi_w [128,256] -> phiT [256,128]
// ---------------------------------------------------------------------------
__global__ void transpose_phi(const float* __restrict__ phi_w) {
    int idx = blockIdx.x * blockDim.x + threadIdx.x;   // 0 .. 32767
    if (idx < C_IN * C_MID) {
        int i = idx >> 7;          // 0..255
        int k = idx & 127;         // 0..127
        d_phiT[idx] = phi_w[k * C_IN + i];
    }
}

// ---------------------------------------------------------------------------
// Batch-independent small vectors: og, tp, q, alpha
// ---------------------------------------------------------------------------
__global__ void prep_vectors(const float* __restrict__ out_w,
                             const float* __restrict__ g_b,
                             const float* __restrict__ theta_w,
                             const float* __restrict__ phi_b,
                             const float* __restrict__ phi_w,
                             const float* __restrict__ theta_b) {
    int tid = threadIdx.x;
    int wid = tid >> 5, lane = tid & 31;

    // og[r] = sum_k out_w[r][k] * g_b[k]   (K=128)
    for (int r = wid; r < C_IN; r += 8) {
        float v = warp_dot(out_w + r * C_MID, g_b, C_MID);
        if (lane == 0) d_og[r] = v;
    }
    // tp[j] = sum_k theta_w[k][j]*phi_b[k] ; q[j] = sum_k phi_w[k][j]*theta_b[k]
    {
        float a = 0.f, b = 0.f;
        for (int k = 0; k < C_MID; k++) {
            a += theta_w[k * C_IN + tid] * phi_b[k];
            b += phi_w[k * C_IN + tid] * theta_b[k];
        }
        d_tp[tid] = a;
        d_q[tid] = b;
    }
    // alpha = phi_b . theta_b
    if (wid == 0) {
        float a = 0.f;
        for (int k = lane; k < C_MID; k += 32) a += phi_b[k] * theta_b[k];
#pragma unroll
        for (int o = 16; o; o >>= 1) a += __shfl_xor_sync(0xffffffffu, a, o);
        if (lane == 0) d_alpha = a;
    }
}

// ---------------------------------------------------------------------------
// Gram kernel: G_b += X_tile X_tile^T over n-chunks (split-K w/ atomics),
// also accumulates s_b = X 1.
// grid: (16 ij-tiles, 16 n-chunks, 4 batch), block 256
// ---------------------------------------------------------------------------
__global__ void __launch_bounds__(256) gram_kernel(const float* __restrict__ x) {
    const int bz = blockIdx.z;
    const int ij = blockIdx.x;
    const int i0 = (ij >> 2) * 64;
    const int j0 = (ij & 3) * 64;
    const int n0 = blockIdx.y * 256;
    const float* X = x + (long)bz * C_IN * NSP;

    __shared__ float As[16][64];
    __shared__ float Bs[16][64];

    const int tid = threadIdx.x;
    const int am = tid >> 2;           // 0..63
    const int ak = (tid & 3) * 4;      // 0,4,8,12
    const int tx = tid & 15, ty = tid >> 4;

    float acc[4][4] = {};
    float srow = 0.f;

    for (int nc = 0; nc < 256; nc += 16) {
        float4 va = *(const float4*)(X + (long)(i0 + am) * NSP + n0 + nc + ak);
        As[ak + 0][am] = va.x; As[ak + 1][am] = va.y;
        As[ak + 2][am] = va.z; As[ak + 3][am] = va.w;
        if (j0 == 0) srow += va.x + va.y + va.z + va.w;

        float4 vb = *(const float4*)(X + (long)(j0 + am) * NSP + n0 + nc + ak);
        Bs[ak + 0][am] = vb.x; Bs[ak + 1][am] = vb.y;
        Bs[ak + 2][am] = vb.z; Bs[ak + 3][am] = vb.w;
        __syncthreads();

#pragma unroll
        for (int k = 0; k < 16; k++) {
            float4 a = *(const float4*)(&As[k][ty * 4]);
            float4 b = *(const float4*)(&Bs[k][tx * 4]);
            acc[0][0] += a.x * b.x; acc[0][1] += a.x * b.y; acc[0][2] += a.x * b.z; acc[0][3] += a.x * b.w;
            acc[1][0] += a.y * b.x; acc[1][1] += a.y * b.y; acc[1][2] += a.y * b.z; acc[1][3] += a.y * b.w;
            acc[2][0] += a.z * b.x; acc[2][1] += a.z * b.y; acc[2][2] += a.z * b.z; acc[2][3] += a.z * b.w;
            acc[3][0] += a.w * b.x; acc[3][1] += a.w * b.y; acc[3][2] += a.w * b.z; acc[3][3] += a.w * b.w;
        }
        __syncthreads();
    }

    float* Gp = d_G + (long)bz * C_IN * C_IN;
#pragma unroll
    for (int i = 0; i < 4; i++)
#pragma unroll
        for (int j = 0; j < 4; j++)
            atomicAdd(&Gp[(i0 + ty * 4 + i) * C_IN + j0 + tx * 4 + j], acc[i][j]);

    if (j0 == 0) atomicAdd(&d_s[bz * C_IN + i0 + am], srow);
}

// ---------------------------------------------------------------------------
// Per-batch small vectors: ws=phi_w s, up=(OG s)/N, Gq=G q, vp=v/N+tp, beta, c
// grid 4 blocks (one per batch), 256 threads
// ---------------------------------------------------------------------------
__global__ void batch_vectors(const float* __restrict__ phi_w,
                              const float* __restrict__ theta_w,
                              const float* __restrict__ theta_b,
                              const float* __restrict__ out_b) {
    const int bz = blockIdx.x;
    const int tid = threadIdx.x, wid = tid >> 5, lane = tid & 31;

    __shared__ float sv[C_IN], qs[C_IN], ws[C_MID], Gq[C_IN];
    __shared__ float sbeta;

    sv[tid] = d_s[bz * C_IN + tid];
    qs[tid] = d_q[tid];
    __syncthreads();

    // ws[r] = phi_w[r,:] . s
    for (int r = wid; r < C_MID; r += 8) {
        float v = warp_dot(phi_w + r * C_IN, sv, C_IN);
        if (lane == 0) ws[r] = v;
    }
    // up[r] = (OG[r,:] . s)/N ;  Gq[r] = G_b[r,:] . q
    for (int r = wid; r < C_IN; r += 8) {
        float u = warp_dot(d_OG + r * C_IN, sv, C_IN);
        if (lane == 0) d_up[bz * C_IN + r] = u * INVN;
        float gq = warp_dot(d_G + (long)bz * C_IN * C_IN + r * C_IN, qs, C_IN);
        if (lane == 0) Gq[r] = gq;
    }
    __syncthreads();

    // vp[j] = (sum_k theta_w[k][j]*ws[k])/N + tp[j]
    {
        float a = 0.f;
        for (int k = 0; k < C_MID; k++) a += theta_w[k * C_IN + tid] * ws[k];
        d_vp[bz * C_IN + tid] = a * INVN + d_tp[tid];
    }
    // beta = ws . theta_b
    if (wid == 0) {
        float a = 0.f;
        for (int k = lane; k < C_MID; k += 32) a += ws[k] * theta_b[k];
#pragma unroll
        for (int o = 16; o; o >>= 1) a += __shfl_xor_sync(0xffffffffu, a, o);
        if (lane == 0) sbeta = a;
    }
    __syncthreads();

    const float alpha = d_alpha;
    for (int r = wid; r < C_IN; r += 8) {
        float t = warp_dot(d_OG + r * C_IN, Gq, C_IN);
        if (lane == 0)
            d_cvec[bz * C_IN + r] = t * INVN + alpha * d_up[bz * C_IN + r] +
                                    (sbeta * INVN + alpha) * d_og[r] + out_b[r];
    }
}

// ---------------------------------------------------------------------------
// Generic 64x64x16 fp32 GEMM. MODE 0: C=A@B
// MODE 1: C = (A@B)*scale + up[i]*tp[j] + og[i]*vp[j]   (epilogue via globals)
// MODE 2: C = A@B + B_resid + c[i]   (residual = B itself, rows 0..255)
// grid (N/64, M/64, batches), block 256
// ---------------------------------------------------------------------------
template <int MODE>
__global__ void __launch_bounds__(256) gemm64(const float* __restrict__ A,
                                              const float* __restrict__ B,
                                              float* __restrict__ C,
                                              int M, int N, int K,
                                              long sA, long sB, long sC,
                                              float scale) {
    const int bz = blockIdx.z;
    A += bz * sA; B += bz * sB; C += bz * sC;
    const int n0 = blockIdx.x * 64;
    const int m0 = blockIdx.y * 64;

    __shared__ float As[16][64];
    __shared__ float Bs[16][64];

    const int tid = threadIdx.x;
    const int am = tid >> 2;          // 0..63
    const int ak = (tid & 3) * 4;     // 0,4,8,12
    const int bk = tid >> 4;          // 0..15
    const int bn = (tid & 15) * 4;
    const int tx = tid & 15, ty = tid >> 4;

    float acc[4][4] = {};

    for (int k0 = 0; k0 < K; k0 += 16) {
        float4 va = *(const float4*)(A + (long)(m0 + am) * K + k0 + ak);
        As[ak + 0][am] = va.x; As[ak + 1][am] = va.y;
        As[ak + 2][am] = va.z; As[ak + 3][am] = va.w;
        *(float4*)(&Bs[bk][bn]) = *(const float4*)(B + (long)(k0 + bk) * N + n0 + bn);
        __syncthreads();

#pragma unroll
        for (int k = 0; k < 16; k++) {
            float4 a = *(const float4*)(&As[k][ty * 4]);
            float4 b = *(const float4*)(&Bs[k][tx * 4]);
            acc[0][0] += a.x * b.x; acc[0][1] += a.x * b.y; acc[0][2] += a.x * b.z; acc[0][3] += a.x * b.w;
            acc[1][0] += a.y * b.x; acc[1][1] += a.y * b.y; acc[1][2] += a.y * b.z; acc[1][3] += a.y * b.w;
            acc[2][0] += a.z * b.x; acc[2][1] += a.z * b.y; acc[2][2] += a.z * b.z; acc[2][3] += a.z * b.w;
            acc[3][0] += a.w * b.x; acc[3][1] += a.w * b.y; acc[3][2] += a.w * b.z; acc[3][3] += a.w * b.w;
        }
        __syncthreads();
    }

    const int cm = m0 + ty * 4;
    const int cn = n0 + tx * 4;

    if (MODE == 0) {
#pragma unroll
        for (int i = 0; i < 4; i++) {
            float4 r = make_float4(acc[i][0], acc[i][1], acc[i][2], acc[i][3]);
            *(float4*)(C + (long)(cm + i) * N + cn) = r;
        }
    } else if (MODE == 1) {
        const float* ub = d_up + bz * C_IN;
        const float* vb = d_vp + bz * C_IN;
        float tp0 = d_tp[cn + 0], tp1 = d_tp[cn + 1], tp2 = d_tp[cn + 2], tp3 = d_tp[cn + 3];
        float vp0 = vb[cn + 0], vp1 = vb[cn + 1], vp2 = vb[cn + 2], vp3 = vb[cn + 3];
#pragma unroll
        for (int i = 0; i < 4; i++) {
            float ui = ub[cm + i], ogi = d_og[cm + i];
            float4 r;
            r.x = acc[i][0] * scale + ui * tp0 + ogi * vp0;
            r.y = acc[i][1] * scale + ui * tp1 + ogi * vp1;
            r.z = acc[i][2] * scale + ui * tp2 + ogi * vp2;
            r.w = acc[i][3] * scale + ui * tp3 + ogi * vp3;
            *(float4*)(C + (long)(cm + i) * N + cn) = r;
        }
    } else { // MODE 2: out = A@X + X + c
        const float* cb = d_cvec + bz * C_IN;
#pragma unroll
        for (int i = 0; i < 4; i++) {
            float4 xr = *(const float4*)(B + (long)(cm + i) * N + cn);
            float ci = cb[cm + i];
            float4 r;
            r.x = acc[i][0] + xr.x + ci;
            r.y = acc[i][1] + xr.y + ci;
            r.z = acc[i][2] + xr.z + ci;
            r.w = acc[i][3] + xr.w + ci;
            *(float4*)(C + (long)(cm + i) * N + cn) = r;
        }
    }
}

// ---------------------------------------------------------------------------
// Host launcher
// ---------------------------------------------------------------------------
extern "C" void kernel_launch(void* const* d_in, const int* in_sizes, int n_in,
                              void* d_out, int out_size) {
    const float* x       = (const float*)d_in[0];
    const float* g_w     = (const float*)d_in[1];
    const float* g_b     = (const float*)d_in[2];
    const float* theta_w = (const float*)d_in[3];
    const float* theta_b = (const float*)d_in[4];
    const float* phi_w   = (const float*)d_in[5];
    const float* phi_b   = (const float*)d_in[6];
    const float* out_w   = (const float*)d_in[7];
    const float* out_b   = (const float*)d_in[8];
    float* out = (float*)d_out;

    float *pG, *pU, *pA, *pOG, *pPT, *pPhiT;
    cudaGetSymbolAddress((void**)&pG, d_G);
    cudaGetSymbolAddress((void**)&pU, d_U);
    cudaGetSymbolAddress((void**)&pA, d_Afold);
    cudaGetSymbolAddress((void**)&pOG, d_OG);
    cudaGetSymbolAddress((void**)&pPT, d_PT);
    cudaGetSymbolAddress((void**)&pPhiT, d_phiT);

    // 1) zero accumulators
    zero_kernel<<<(BATCH * C_IN * C_IN + 255) / 256, 256>>>();
    // 2) phi_w^T
    transpose_phi<<<(C_IN * C_MID + 255) / 256, 256>>>(phi_w);
    // 3) OG = out_w @ g_w   [256,256] K=128
    gemm64<0><<<dim3(4, 4, 1), 256>>>(out_w, g_w, pOG, 256, 256, 128, 0, 0, 0, 1.f);
    // 4) PT = phi_w^T @ theta_w   [256,256] K=128
    gemm64<0><<<dim3(4, 4, 1), 256>>>(pPhiT, theta_w, pPT, 256, 256, 128, 0, 0, 0, 1.f);
    // 5) batch-independent vectors
    prep_vectors<<<1, 256>>>(out_w, g_b, theta_w, phi_b, phi_w, theta_b);
    // 6) Gram + row sums
    gram_kernel<<<dim3(16, 16, BATCH), 256>>>(x);
    // 7) per-batch vectors (up, vp, c)
    batch_vectors<<<BATCH, 256>>>(phi_w, theta_w, theta_b, out_b);
    // 8) U_b = OG @ G_b
    gemm64<0><<<dim3(4, 4, BATCH), 256>>>(pOG, pG, pU, 256, 256, 256,
                                          0, (long)C_IN * C_IN, (long)C_IN * C_IN, 1.f);
    // 9) A_b = (U_b @ PT)/N + up⊗tp + og⊗vp
    gemm64<1><<<dim3(4, 4, BATCH), 256>>>(pU, pPT, pA, 256, 256, 256,
                                          (long)C_IN * C_IN, 0, (long)C_IN * C_IN, INVN);
    // 10) out_b = A_b @ X_b + X_b + c_b
    gemm64<2><<<dim3(64, 4, BATCH), 256>>>(pA, x, out, 256, NSP, 256,
                                           (long)C_IN * C_IN, (long)C_IN * NSP,
                                           (long)C_IN * NSP, 1.f);
}

// round 2
// speedup vs baseline: 1.5068x; 1.5068x over previous
#include <cuda_runtime.h>
#include <cuda_bf16.h>
#include <cstdint>

// Problem constants
#define BATCH 4
#define C_IN 256
#define C_MID 128
#define NSP 4096            // 64*64 spatial
#define INVN (1.0f/4096.0f)

// ---------------------------------------------------------------------------
// Device scratch (no allocations allowed)
// ---------------------------------------------------------------------------
__device__ __align__(256) float d_G[BATCH * C_IN * C_IN];    // Gram X X^T per batch
__device__ __align__(256) float d_s[BATCH * C_IN];           // row sums X*1
__device__ __align__(256) float d_U[BATCH * C_IN * C_IN];    // OG @ G
__device__ __align__(256) float d_Afold[BATCH * C_IN * C_IN];// folded operator A_b
__device__ __align__(256) float d_OG[C_IN * C_IN];           // out_w @ g_w
__device__ __align__(256) float d_PT[C_IN * C_IN];           // phi_w^T @ theta_w
__device__ __align__(256) float d_og[C_IN];                  // out_w @ g_b
__device__ __align__(256) float d_tp[C_IN];                  // theta_w^T @ phi_b
__device__ __align__(256) float d_q[C_IN];                   // phi_w^T @ theta_b
__device__ __align__(256) float d_up[BATCH * C_IN];          // (OG @ s)/N
__device__ __align__(256) float d_vp[BATCH * C_IN];          // v/N + tp
__device__ __align__(256) float d_cvec[BATCH * C_IN];        // per-batch bias c
__device__ float d_alpha;                                    // phi_b . theta_b

// lower-triangle tile enumeration for Gram (4x4 tile grid)
__constant__ unsigned char c_TI[10] = {0,1,1,2,2,2,3,3,3,3};
__constant__ unsigned char c_TJ[10] = {0,0,1,0,1,2,0,1,2,3};

// ---------------------------------------------------------------------------
// Helpers
// ---------------------------------------------------------------------------
__device__ __forceinline__ uint32_t f2tf32(float f) {
    uint32_t u;
    asm("cvt.rna.tf32.f32 %0, %1;" : "=r"(u) : "f"(f));
    return u;
}

__device__ __forceinline__ void mma_tf32(float c[4],
                                         uint32_t a0, uint32_t a1, uint32_t a2, uint32_t a3,
                                         uint32_t b0, uint32_t b1) {
    asm volatile("mma.sync.aligned.m16n8k8.row.col.f32.tf32.tf32.f32 "
                 "{%0,%1,%2,%3}, {%4,%5,%6,%7}, {%8,%9}, {%0,%1,%2,%3};"
                 : "+f"(c[0]), "+f"(c[1]), "+f"(c[2]), "+f"(c[3])
                 : "r"(a0), "r"(a1), "r"(a2), "r"(a3), "r"(b0), "r"(b1));
}

__device__ __forceinline__ float warp_dot(const float* __restrict__ row,
                                          const float* __restrict__ v, int K) {
    int lane = threadIdx.x & 31;
    float a = 0.f;
    for (int k = lane; k < K; k += 32) a += row[k] * v[k];
#pragma unroll
    for (int o = 16; o; o >>= 1) a += __shfl_xor_sync(0xffffffffu, a, o);
    return a;
}

// ---------------------------------------------------------------------------
// setup_misc: block 0 computes batch-independent vectors; blocks 1.. zero G,s
// ---------------------------------------------------------------------------
__global__ void __launch_bounds__(256) setup_misc(const float* __restrict__ out_w,
                                                  const float* __restrict__ g_b,
                                                  const float* __restrict__ theta_w,
                                                  const float* __restrict__ phi_b,
                                                  const float* __restrict__ phi_w,
                                                  const float* __restrict__ theta_b) {
    const int tid = threadIdx.x;
    if (blockIdx.x == 0) {
        const int wid = tid >> 5, lane = tid & 31;
        for (int r = wid; r < C_IN; r += 8) {
            float v = warp_dot(out_w + r * C_MID, g_b, C_MID);
            if (lane == 0) d_og[r] = v;
        }
        {
            float a = 0.f, b = 0.f;
            for (int k = 0; k < C_MID; k++) {
                a += theta_w[k * C_IN + tid] * phi_b[k];
                b += phi_w[k * C_IN + tid] * theta_b[k];
            }
            d_tp[tid] = a;
            d_q[tid] = b;
        }
        if (wid == 0) {
            float a = 0.f;
            for (int k = lane; k < C_MID; k += 32) a += phi_b[k] * theta_b[k];
#pragma unroll
            for (int o = 16; o; o >>= 1) a += __shfl_xor_sync(0xffffffffu, a, o);
            if (lane == 0) d_alpha = a;
        }
    } else {
        const int nb = gridDim.x - 1;
        const int bi = blockIdx.x - 1;
        for (int idx = bi * 256 + tid; idx < BATCH * C_IN * C_IN; idx += nb * 256)
            d_G[idx] = 0.f;
        for (int idx = bi * 256 + tid; idx < BATCH * C_IN; idx += nb * 256)
            d_s[idx] = 0.f;
    }
}

// ---------------------------------------------------------------------------
// SIMT 32x32-tile fp32 GEMM body (small matrices). C is [*,256] row-major.
// mode 0: C = A@B.   mode 1: C = A@B*INVN + up[i]*tp[j] + og[i]*vp[j]
// ---------------------------------------------------------------------------
__device__ __forceinline__ void gemm32_body(const float* __restrict__ A, int lda, bool atrans,
                                            const float* __restrict__ B,
                                            float* __restrict__ C, int K, int mode, int bz) {
    __shared__ float As[32][33];
    __shared__ float Bs[32][33];
    const int tid = threadIdx.x;
    const int j0 = blockIdx.x * 32, i0 = blockIdx.y * 32;
    const int tx = tid & 15, ty = tid >> 4;
    const int lr = tid >> 3, lc = (tid & 7) * 4;

    float a00 = 0.f, a01 = 0.f, a10 = 0.f, a11 = 0.f;

    for (int k0 = 0; k0 < K; k0 += 32) {
        float4 va;
        if (!atrans) va = *(const float4*)(A + (size_t)(i0 + lr) * lda + k0 + lc);
        else         va = *(const float4*)(A + (size_t)(k0 + lr) * lda + i0 + lc);
        float4 vb = *(const float4*)(B + (size_t)(k0 + lr) * 256 + j0 + lc);
        __syncthreads();
        if (!atrans) {
            As[lc + 0][lr] = va.x; As[lc + 1][lr] = va.y;
            As[lc + 2][lr] = va.z; As[lc + 3][lr] = va.w;
        } else {
            As[lr][lc + 0] = va.x; As[lr][lc + 1] = va.y;
            As[lr][lc + 2] = va.z; As[lr][lc + 3] = va.w;
        }
        Bs[lr][lc + 0] = vb.x; Bs[lr][lc + 1] = vb.y;
        Bs[lr][lc + 2] = vb.z; Bs[lr][lc + 3] = vb.w;
        __syncthreads();
#pragma unroll
        for (int k = 0; k < 32; k++) {
            float av0 = As[k][ty * 2], av1 = As[k][ty * 2 + 1];
            float bv0 = Bs[k][tx * 2], bv1 = Bs[k][tx * 2 + 1];
            a00 += av0 * bv0; a01 += av0 * bv1;
            a10 += av1 * bv0; a11 += av1 * bv1;
        }
    }

    const int i = i0 + ty * 2, j = j0 + tx * 2;
    if (mode == 0) {
        C[(size_t)i * 256 + j] = a00;       C[(size_t)i * 256 + j + 1] = a01;
        C[(size_t)(i + 1) * 256 + j] = a10; C[(size_t)(i + 1) * 256 + j + 1] = a11;
    } else {
        const float* ub = d_up + bz * C_IN;
        const float* vb2 = d_vp + bz * C_IN;
        float u0 = ub[i], u1 = ub[i + 1], o0 = d_og[i], o1 = d_og[i + 1];
        float t0 = d_tp[j], t1 = d_tp[j + 1], v0 = vb2[j], v1 = vb2[j + 1];
        C[(size_t)i * 256 + j]           = a00 * INVN + u0 * t0 + o0 * v0;
        C[(size_t)i * 256 + j + 1]       = a01 * INVN + u0 * t1 + o0 * v1;
        C[(size_t)(i + 1) * 256 + j]     = a10 * INVN + u1 * t0 + o1 * v0;
        C[(size_t)(i + 1) * 256 + j + 1] = a11 * INVN + u1 * t1 + o1 * v1;
    }
}

// OG (z=0) and PT (z=1) in one launch, grid (8,8,2)
__global__ void __launch_bounds__(256) wgemm_small(const float* __restrict__ out_w,
                                                   const float* __restrict__ g_w,
                                                   const float* __restrict__ phi_w,
                                                   const float* __restrict__ theta_w) {
    if (blockIdx.z == 0) gemm32_body(out_w, C_MID, false, g_w, d_OG, C_MID, 0, 0);
    else                 gemm32_body(phi_w, C_IN, true, theta_w, d_PT, C_MID, 0, 0);
}

// batched small GEMM, grid (8,8,BATCH)
template <int MODE>
__global__ void __launch_bounds__(256) gemm32k(const float* __restrict__ A,
                                               const float* __restrict__ B,
                                               float* __restrict__ C, int K,
                                               long sA, long sB, long sC) {
    const int bz = blockIdx.z;
    gemm32_body(A + bz * sA, K, false, B + bz * sB, C + bz * sC, K, MODE, bz);
}

// ---------------------------------------------------------------------------
// Gram via tf32 tensor cores. Lower-triangle tiles + mirror, split-K=4.
// grid (10 tiles, 4 k-chunks, 4 batch), block 256 (8 warps: 2m x 4n)
// Also accumulates row sums s (tiles with tj==0).
// ---------------------------------------------------------------------------
__global__ void __launch_bounds__(256) gram_tc(const float* __restrict__ x) {
    const int t = blockIdx.x;
    const int ti = c_TI[t], tj = c_TJ[t];
    const int i0 = ti * 64, j0 = tj * 64;
    const int kbase = blockIdx.y * 1024;
    const int bz = blockIdx.z;
    const float* X = x + (size_t)bz * C_IN * NSP;

    __shared__ uint32_t As[64 * 36];
    __shared__ uint32_t Bs[64 * 36];

    const int tid = threadIdx.x;
    const int lane = tid & 31, warp = tid >> 5;
    const int wm = warp >> 2, wn = warp & 3;   // warp grid 2 x 4
    const int lr = tid >> 3;                    // 0..31
    const int lc = (tid & 7) * 4;               // 0..28
    const int gq = lane >> 2, tg = lane & 3;    // frag row group / col group

    float acc[2][2][4] = {};
    float s0 = 0.f, s1 = 0.f;
    const bool do_s = (tj == 0);

    for (int k0 = 0; k0 < 1024; k0 += 32) {
        const float* ap0 = X + (size_t)(i0 + lr) * NSP + kbase + k0 + lc;
        const float* ap1 = X + (size_t)(i0 + lr + 32) * NSP + kbase + k0 + lc;
        const float* bp0 = X + (size_t)(j0 + lr) * NSP + kbase + k0 + lc;
        const float* bp1 = X + (size_t)(j0 + lr + 32) * NSP + kbase + k0 + lc;
        float4 va0 = *(const float4*)ap0;
        float4 va1 = *(const float4*)ap1;
        float4 vb0 = *(const float4*)bp0;
        float4 vb1 = *(const float4*)bp1;
        if (do_s) {
            s0 += va0.x + va0.y + va0.z + va0.w;
            s1 += va1.x + va1.y + va1.z + va1.w;
        }
        __syncthreads();
        *(uint4*)&As[lr * 36 + lc] = make_uint4(f2tf32(va0.x), f2tf32(va0.y), f2tf32(va0.z), f2tf32(va0.w));
        *(uint4*)&As[(lr + 32) * 36 + lc] = make_uint4(f2tf32(va1.x), f2tf32(va1.y), f2tf32(va1.z), f2tf32(va1.w));
        *(uint4*)&Bs[lr * 36 + lc] = make_uint4(f2tf32(vb0.x), f2tf32(vb0.y), f2tf32(vb0.z), f2tf32(vb0.w));
        *(uint4*)&Bs[(lr + 32) * 36 + lc] = make_uint4(f2tf32(vb1.x), f2tf32(vb1.y), f2tf32(vb1.z), f2tf32(vb1.w));
        __syncthreads();
#pragma unroll
        for (int kk = 0; kk < 32; kk += 8) {
            uint32_t a[2][4], b[2][2];
#pragma unroll
            for (int ma = 0; ma < 2; ma++) {
                int rb = wm * 32 + ma * 16 + gq;
                a[ma][0] = As[rb * 36 + kk + tg];
                a[ma][1] = As[(rb + 8) * 36 + kk + tg];
                a[ma][2] = As[rb * 36 + kk + 4 + tg];
                a[ma][3] = As[(rb + 8) * 36 + kk + 4 + tg];
            }
#pragma unroll
            for (int na = 0; na < 2; na++) {
                int cb = wn * 16 + na * 8 + gq;
                b[na][0] = Bs[cb * 36 + kk + tg];
                b[na][1] = Bs[cb * 36 + kk + 4 + tg];
            }
#pragma unroll
            for (int ma = 0; ma < 2; ma++)
#pragma unroll
                for (int na = 0; na < 2; na++)
                    mma_tf32(acc[ma][na], a[ma][0], a[ma][1], a[ma][2], a[ma][3],
                             b[na][0], b[na][1]);
        }
    }

    float* Gp = d_G + (size_t)bz * C_IN * C_IN;
#pragma unroll
    for (int ma = 0; ma < 2; ma++) {
        int rr = i0 + wm * 32 + ma * 16 + gq;
#pragma unroll
        for (int na = 0; na < 2; na++) {
            int cn = j0 + wn * 16 + na * 8 + 2 * tg;
            atomicAdd(&Gp[(size_t)rr * 256 + cn],           acc[ma][na][0]);
            atomicAdd(&Gp[(size_t)rr * 256 + cn + 1],       acc[ma][na][1]);
            atomicAdd(&Gp[(size_t)(rr + 8) * 256 + cn],     acc[ma][na][2]);
            atomicAdd(&Gp[(size_t)(rr + 8) * 256 + cn + 1], acc[ma][na][3]);
            if (ti != tj) {
                atomicAdd(&Gp[(size_t)cn * 256 + rr],           acc[ma][na][0]);
                atomicAdd(&Gp[(size_t)(cn + 1) * 256 + rr],     acc[ma][na][1]);
                atomicAdd(&Gp[(size_t)cn * 256 + rr + 8],       acc[ma][na][2]);
                atomicAdd(&Gp[(size_t)(cn + 1) * 256 + rr + 8], acc[ma][na][3]);
            }
        }
    }
    if (do_s) {
        atomicAdd(&d_s[bz * C_IN + i0 + lr], s0);
        atomicAdd(&d_s[bz * C_IN + i0 + lr + 32], s1);
    }
}

// ---------------------------------------------------------------------------
// Per-batch small vectors: ws=phi_w s, up=(OG s)/N, Gq=G q, vp=v/N+tp, beta, c
// ---------------------------------------------------------------------------
__global__ void __launch_bounds__(256) batch_vectors(const float* __restrict__ phi_w,
                                                     const float* __restrict__ theta_w,
                                                     const float* __restrict__ theta_b,
                                                     const float* __restrict__ out_b) {
    const int bz = blockIdx.x;
    const int tid = threadIdx.x, wid = tid >> 5, lane = tid & 31;

    __shared__ float sv[C_IN], qs[C_IN], ws[C_MID], Gq[C_IN];
    __shared__ float sbeta;

    sv[tid] = d_s[bz * C_IN + tid];
    qs[tid] = d_q[tid];
    __syncthreads();

    for (int r = wid; r < C_MID; r += 8) {
        float v = warp_dot(phi_w + r * C_IN, sv, C_IN);
        if (lane == 0) ws[r] = v;
    }
    for (int r = wid; r < C_IN; r += 8) {
        float u = warp_dot(d_OG + r * C_IN, sv, C_IN);
        if (lane == 0) d_up[bz * C_IN + r] = u * INVN;
        float gqv = warp_dot(d_G + (size_t)bz * C_IN * C_IN + r * C_IN, qs, C_IN);
        if (lane == 0) Gq[r] = gqv;
    }
    __syncthreads();

    {
        float a = 0.f;
        for (int k = 0; k < C_MID; k++) a += theta_w[k * C_IN + tid] * ws[k];
        d_vp[bz * C_IN + tid] = a * INVN + d_tp[tid];
    }
    if (wid == 0) {
        float a = 0.f;
        for (int k = lane; k < C_MID; k += 32) a += ws[k] * theta_b[k];
#pragma unroll
        for (int o = 16; o; o >>= 1) a += __shfl_xor_sync(0xffffffffu, a, o);
        if (lane == 0) sbeta = a;
    }
    __syncthreads();

    const float alpha = d_alpha;
    for (int r = wid; r < C_IN; r += 8) {
        float tv = warp_dot(d_OG + r * C_IN, Gq, C_IN);
        if (lane == 0)
            d_cvec[bz * C_IN + r] = tv * INVN + alpha * d_up[bz * C_IN + r] +
                                    (sbeta * INVN + alpha) * d_og[r] + out_b[r];
    }
}

// ---------------------------------------------------------------------------
// Final GEMM via tf32 tensor cores: out = Afold @ X + X + c
// grid (32 n-tiles of 128, 4 m-tiles of 64, 4 batch), block 256 (2m x 4n warps)
// ---------------------------------------------------------------------------
__global__ void __launch_bounds__(256) final_tc(const float* __restrict__ x,
                                                float* __restrict__ out) {
    const int n0 = blockIdx.x * 128;
    const int m0 = blockIdx.y * 64;
    const int bz = blockIdx.z;
    const float* Ab = d_Afold + (size_t)bz * C_IN * C_IN;
    const float* Xb = x + (size_t)bz * C_IN * NSP;
    float* Ob = out + (size_t)bz * C_IN * NSP;

    __shared__ uint32_t As[64 * 36];
    __shared__ uint32_t Bs[32 * 136];

    const int tid = threadIdx.x;
    const int lane = tid & 31, warp = tid >> 5;
    const int wm = warp >> 2, wn = warp & 3;    // 2 x 4 warps
    const int gq = lane >> 2, tg = lane & 3;

    // A-tile load indices (64 rows x 32 k)
    const int alr = tid >> 3;                  // 0..31 (rows alr, alr+32)
    const int alc = (tid & 7) * 4;
    // B-tile load indices (32 k-rows x 128 n)
    const int blr = tid >> 3;                  // hmm need 32 rows x 32 f4cols
    const int bf4 = (tid & 7);                 // + 8*i

    float acc[2][4][4] = {};

    for (int k0 = 0; k0 < 256; k0 += 32) {
        float4 va0 = *(const float4*)(Ab + (size_t)(m0 + alr) * 256 + k0 + alc);
        float4 va1 = *(const float4*)(Ab + (size_t)(m0 + alr + 32) * 256 + k0 + alc);
        float4 vb[4];
#pragma unroll
        for (int i = 0; i < 4; i++) {
            int fc = (bf4 + 8 * i) * 4;
            vb[i] = *(const float4*)(Xb + (size_t)(k0 + blr) * NSP + n0 + fc);
        }
        __syncthreads();
        *(uint4*)&As[alr * 36 + alc] = make_uint4(f2tf32(va0.x), f2tf32(va0.y), f2tf32(va0.z), f2tf32(va0.w));
        *(uint4*)&As[(alr + 32) * 36 + alc] = make_uint4(f2tf32(va1.x), f2tf32(va1.y), f2tf32(va1.z), f2tf32(va1.w));
#pragma unroll
        for (int i = 0; i < 4; i++) {
            int fc = (bf4 + 8 * i) * 4;
            *(uint4*)&Bs[blr * 136 + fc] = make_uint4(f2tf32(vb[i].x), f2tf32(vb[i].y), f2tf32(vb[i].z), f2tf32(vb[i].w));
        }
        __syncthreads();
#pragma unroll
        for (int kk = 0; kk < 32; kk += 8) {
            uint32_t a[2][4], b[4][2];
#pragma unroll
            for (int ma = 0; ma < 2; ma++) {
                int rb = wm * 32 + ma * 16 + gq;
                a[ma][0] = As[rb * 36 + kk + tg];
                a[ma][1] = As[(rb + 8) * 36 + kk + tg];
                a[ma][2] = As[rb * 36 + kk + 4 + tg];
                a[ma][3] = As[(rb + 8) * 36 + kk + 4 + tg];
            }
#pragma unroll
            for (int na = 0; na < 4; na++) {
                int cb = wn * 32 + na * 8 + gq;
                b[na][0] = Bs[(kk + tg) * 136 + cb];
                b[na][1] = Bs[(kk + 4 + tg) * 136 + cb];
            }
#pragma unroll
            for (int ma = 0; ma < 2; ma++)
#pragma unroll
                for (int na = 0; na < 4; na++)
                    mma_tf32(acc[ma][na], a[ma][0], a[ma][1], a[ma][2], a[ma][3],
                             b[na][0], b[na][1]);
        }
    }

    // Epilogue: + X + c, write out
    const float* cb = d_cvec + bz * C_IN;
#pragma unroll
    for (int ma = 0; ma < 2; ma++) {
        int rm = m0 + wm * 32 + ma * 16 + gq;
        float ci0 = cb[rm], ci1 = cb[rm + 8];
#pragma unroll
        for (int na = 0; na < 4; na++) {
            int cn = n0 + wn * 32 + na * 8 + 2 * tg;
            float2 x0 = *(const float2*)(Xb + (size_t)rm * NSP + cn);
            float2 x1 = *(const float2*)(Xb + (size_t)(rm + 8) * NSP + cn);
            float2 o0 = make_float2(acc[ma][na][0] + x0.x + ci0, acc[ma][na][1] + x0.y + ci0);
            float2 o1 = make_float2(acc[ma][na][2] + x1.x + ci1, acc[ma][na][3] + x1.y + ci1);
            *(float2*)(Ob + (size_t)rm * NSP + cn) = o0;
            *(float2*)(Ob + (size_t)(rm + 8) * NSP + cn) = o1;
        }
    }
}

// ---------------------------------------------------------------------------
// Host launcher
// ---------------------------------------------------------------------------
extern "C" void kernel_launch(void* const* d_in, const int* in_sizes, int n_in,
                              void* d_out, int out_size) {
    const float* x       = (const float*)d_in[0];
    const float* g_w     = (const float*)d_in[1];
    const float* g_b     = (const float*)d_in[2];
    const float* theta_w = (const float*)d_in[3];
    const float* theta_b = (const float*)d_in[4];
    const float* phi_w   = (const float*)d_in[5];
    const float* phi_b   = (const float*)d_in[6];
    const float* out_w   = (const float*)d_in[7];
    const float* out_b   = (const float*)d_in[8];
    float* out = (float*)d_out;

    float *pG, *pU, *pA, *pOG, *pPT;
    cudaGetSymbolAddress((void**)&pG, d_G);
    cudaGetSymbolAddress((void**)&pU, d_U);
    cudaGetSymbolAddress((void**)&pA, d_Afold);
    cudaGetSymbolAddress((void**)&pOG, d_OG);
    cudaGetSymbolAddress((void**)&pPT, d_PT);

    const long CC = (long)C_IN * C_IN;

    // 1) zero G/s + batch-independent vectors
    setup_misc<<<64, 256>>>(out_w, g_b, theta_w, phi_b, phi_w, theta_b);
    // 2) OG = out_w @ g_w ; PT = phi_w^T @ theta_w
    wgemm_small<<<dim3(8, 8, 2), 256>>>(out_w, g_w, phi_w, theta_w);
    // 3) Gram (tensor cores, triangle + mirror, split-K) + row sums
    gram_tc<<<dim3(10, 4, BATCH), 256>>>(x);
    // 4) per-batch vectors (up, vp, c)
    batch_vectors<<<BATCH, 256>>>(phi_w, theta_w, theta_b, out_b);
    // 5) U_b = OG @ G_b
    gemm32k<0><<<dim3(8, 8, BATCH), 256>>>(pOG, pG, pU, 256, 0, CC, CC);
    // 6) A_b = (U_b @ PT)/N + up⊗tp + og⊗vp
    gemm32k<1><<<dim3(8, 8, BATCH), 256>>>(pU, pPT, pA, 256, CC, 0, CC);
    // 7) out_b = A_b @ X_b + X_b + c_b  (tensor cores)
    final_tc<<<dim3(32, 4, BATCH), 256>>>(x, out);
}

// round 3
// speedup vs baseline: 2.5080x; 1.6645x over previous
#include <cuda_runtime.h>
#include <cuda_bf16.h>
#include <cstdint>

// Problem constants
#define BATCH 4
#define C_IN 256
#define C_MID 128
#define NSP 4096            // 64*64 spatial
#define INVN (1.0f/4096.0f)

// ---------------------------------------------------------------------------
// Device scratch (no allocations allowed)
// ---------------------------------------------------------------------------
__device__ __align__(256) float d_G[BATCH * C_IN * C_IN];    // Gram X X^T per batch
__device__ __align__(256) float d_s[BATCH * C_IN];           // row sums X*1
__device__ __align__(256) float d_U[BATCH * C_IN * C_IN];    // OG @ G
__device__ __align__(256) float d_Afold[BATCH * C_IN * C_IN];// folded operator A_b
__device__ __align__(256) float d_OG[C_IN * C_IN];           // out_w @ g_w
__device__ __align__(256) float d_PT[C_IN * C_IN];           // phi_w^T @ theta_w
__device__ __align__(256) float d_og[C_IN];                  // out_w @ g_b
__device__ __align__(256) float d_tp[C_IN];                  // theta_w^T @ phi_b
__device__ __align__(256) float d_q[C_IN];                   // phi_w^T @ theta_b
__device__ __align__(256) float d_up[BATCH * C_IN];          // (OG @ s)/N
__device__ __align__(256) float d_vp[BATCH * C_IN];          // v/N + tp
__device__ __align__(256) float d_cvec[BATCH * C_IN];        // per-batch bias c
__device__ __align__(256) float d_ws[BATCH * C_MID];         // phi_w @ s
__device__ __align__(256) float d_Gq[BATCH * C_IN];          // G @ q
__device__ __align__(256) float d_beta[BATCH];               // s . q
__device__ float d_alpha;                                    // phi_b . theta_b

// lower-triangle tile enumeration for Gram (4x4 tile grid)
__constant__ unsigned char c_TI[10] = {0,1,1,2,2,2,3,3,3,3};
__constant__ unsigned char c_TJ[10] = {0,0,1,0,1,2,0,1,2,3};

// ---------------------------------------------------------------------------
// Helpers
// ---------------------------------------------------------------------------
__device__ __forceinline__ uint32_t f2tf32(float f) {
    uint32_t u;
    asm("cvt.rna.tf32.f32 %0, %1;" : "=r"(u) : "f"(f));
    return u;
}

__device__ __forceinline__ void mma_tf32(float c[4],
                                         uint32_t a0, uint32_t a1, uint32_t a2, uint32_t a3,
                                         uint32_t b0, uint32_t b1) {
    asm volatile("mma.sync.aligned.m16n8k8.row.col.f32.tf32.tf32.f32 "
                 "{%0,%1,%2,%3}, {%4,%5,%6,%7}, {%8,%9}, {%0,%1,%2,%3};"
                 : "+f"(c[0]), "+f"(c[1]), "+f"(c[2]), "+f"(c[3])
                 : "r"(a0), "r"(a1), "r"(a2), "r"(a3), "r"(b0), "r"(b1));
}

__device__ __forceinline__ float warp_dot(const float* __restrict__ row,
                                          const float* __restrict__ v, int K) {
    int lane = threadIdx.x & 31;
    float a = 0.f;
    for (int k = lane; k < K; k += 32) a += row[k] * v[k];
#pragma unroll
    for (int o = 16; o; o >>= 1) a += __shfl_xor_sync(0xffffffffu, a, o);
    return a;
}

// vectorized warp-dot over 256 elems: 2 float4 loads per lane
__device__ __forceinline__ float warp_dot256(const float* __restrict__ row,
                                             const float* __restrict__ v) {
    int lane = threadIdx.x & 31;
    float4 r0 = *(const float4*)(row + lane * 4);
    float4 r1 = *(const float4*)(row + 128 + lane * 4);
    float4 v0 = *(const float4*)(v + lane * 4);
    float4 v1 = *(const float4*)(v + 128 + lane * 4);
    float a = r0.x * v0.x + r0.y * v0.y + r0.z * v0.z + r0.w * v0.w
            + r1.x * v1.x + r1.y * v1.y + r1.z * v1.z + r1.w * v1.w;
#pragma unroll
    for (int o = 16; o; o >>= 1) a += __shfl_xor_sync(0xffffffffu, a, o);
    return a;
}

// ---------------------------------------------------------------------------
// setup_misc: block 0 computes batch-independent vectors; blocks 1.. zero G,s
// ---------------------------------------------------------------------------
__global__ void __launch_bounds__(256) setup_misc(const float* __restrict__ out_w,
                                                  const float* __restrict__ g_b,
                                                  const float* __restrict__ theta_w,
                                                  const float* __restrict__ phi_b,
                                                  const float* __restrict__ phi_w,
                                                  const float* __restrict__ theta_b) {
    const int tid = threadIdx.x;
    if (blockIdx.x == 0) {
        const int wid = tid >> 5, lane = tid & 31;
        for (int r = wid; r < C_IN; r += 8) {
            float v = warp_dot(out_w + r * C_MID, g_b, C_MID);
            if (lane == 0) d_og[r] = v;
        }
        {
            float a = 0.f, b = 0.f;
            for (int k = 0; k < C_MID; k++) {
                a += theta_w[k * C_IN + tid] * phi_b[k];
                b += phi_w[k * C_IN + tid] * theta_b[k];
            }
            d_tp[tid] = a;
            d_q[tid] = b;
        }
        if (wid == 0) {
            float a = 0.f;
            for (int k = lane; k < C_MID; k += 32) a += phi_b[k] * theta_b[k];
#pragma unroll
            for (int o = 16; o; o >>= 1) a += __shfl_xor_sync(0xffffffffu, a, o);
            if (lane == 0) d_alpha = a;
        }
    } else {
        const int nb = gridDim.x - 1;
        const int bi = blockIdx.x - 1;
        for (int idx = bi * 256 + tid; idx < BATCH * C_IN * C_IN; idx += nb * 256)
            d_G[idx] = 0.f;
        for (int idx = bi * 256 + tid; idx < BATCH * C_IN; idx += nb * 256)
            d_s[idx] = 0.f;
    }
}

// ---------------------------------------------------------------------------
// SIMT 32x32-tile fp32 GEMM body (small matrices). C is [*,256] row-major.
// mode 0: C = A@B.   mode 1: C = A@B*INVN + up[i]*tp[j] + og[i]*vp[j]
// ---------------------------------------------------------------------------
__device__ __forceinline__ void gemm32_body(const float* __restrict__ A, int lda, bool atrans,
                                            const float* __restrict__ B,
                                            float* __restrict__ C, int K, int mode, int bz) {
    __shared__ float As[32][33];
    __shared__ float Bs[32][33];
    const int tid = threadIdx.x;
    const int j0 = blockIdx.x * 32, i0 = blockIdx.y * 32;
    const int tx = tid & 15, ty = tid >> 4;
    const int lr = tid >> 3, lc = (tid & 7) * 4;

    float a00 = 0.f, a01 = 0.f, a10 = 0.f, a11 = 0.f;

    for (int k0 = 0; k0 < K; k0 += 32) {
        float4 va;
        if (!atrans) va = *(const float4*)(A + (size_t)(i0 + lr) * lda + k0 + lc);
        else         va = *(const float4*)(A + (size_t)(k0 + lr) * lda + i0 + lc);
        float4 vb = *(const float4*)(B + (size_t)(k0 + lr) * 256 + j0 + lc);
        __syncthreads();
        if (!atrans) {
            As[lc + 0][lr] = va.x; As[lc + 1][lr] = va.y;
            As[lc + 2][lr] = va.z; As[lc + 3][lr] = va.w;
        } else {
            As[lr][lc + 0] = va.x; As[lr][lc + 1] = va.y;
            As[lr][lc + 2] = va.z; As[lr][lc + 3] = va.w;
        }
        Bs[lr][lc + 0] = vb.x; Bs[lr][lc + 1] = vb.y;
        Bs[lr][lc + 2] = vb.z; Bs[lr][lc + 3] = vb.w;
        __syncthreads();
#pragma unroll
        for (int k = 0; k < 32; k++) {
            float av0 = As[k][ty * 2], av1 = As[k][ty * 2 + 1];
            float bv0 = Bs[k][tx * 2], bv1 = Bs[k][tx * 2 + 1];
            a00 += av0 * bv0; a01 += av0 * bv1;
            a10 += av1 * bv0; a11 += av1 * bv1;
        }
    }

    const int i = i0 + ty * 2, j = j0 + tx * 2;
    if (mode == 0) {
        C[(size_t)i * 256 + j] = a00;       C[(size_t)i * 256 + j + 1] = a01;
        C[(size_t)(i + 1) * 256 + j] = a10; C[(size_t)(i + 1) * 256 + j + 1] = a11;
    } else {
        const float* ub = d_up + bz * C_IN;
        const float* vb2 = d_vp + bz * C_IN;
        float u0 = ub[i], u1 = ub[i + 1], o0 = d_og[i], o1 = d_og[i + 1];
        float t0 = d_tp[j], t1 = d_tp[j + 1], v0 = vb2[j], v1 = vb2[j + 1];
        C[(size_t)i * 256 + j]           = a00 * INVN + u0 * t0 + o0 * v0;
        C[(size_t)i * 256 + j + 1]       = a01 * INVN + u0 * t1 + o0 * v1;
        C[(size_t)(i + 1) * 256 + j]     = a10 * INVN + u1 * t0 + o1 * v0;
        C[(size_t)(i + 1) * 256 + j + 1] = a11 * INVN + u1 * t1 + o1 * v1;
    }
}

// OG (z=0) and PT (z=1) in one launch, grid (8,8,2)
__global__ void __launch_bounds__(256) wgemm_small(const float* __restrict__ out_w,
                                                   const float* __restrict__ g_w,
                                                   const float* __restrict__ phi_w,
                                                   const float* __restrict__ theta_w) {
    if (blockIdx.z == 0) gemm32_body(out_w, C_MID, false, g_w, d_OG, C_MID, 0, 0);
    else                 gemm32_body(phi_w, C_IN, true, theta_w, d_PT, C_MID, 0, 0);
}

// batched small GEMM, grid (8,8,BATCH)
template <int MODE>
__global__ void __launch_bounds__(256) gemm32k(const float* __restrict__ A,
                                               const float* __restrict__ B,
                                               float* __restrict__ C, int K,
                                               long sA, long sB, long sC) {
    const int bz = blockIdx.z;
    gemm32_body(A + bz * sA, K, false, B + bz * sB, C + bz * sC, K, MODE, bz);
}

// ---------------------------------------------------------------------------
// Gram via tf32 tensor cores. Lower-triangle tiles + mirror, split-K=4.
// grid (10 tiles, 4 k-chunks, 4 batch), block 256 (8 warps: 2m x 4n)
// Also accumulates row sums s (tiles with tj==0).
// ---------------------------------------------------------------------------
__global__ void __launch_bounds__(256) gram_tc(const float* __restrict__ x) {
    const int t = blockIdx.x;
    const int ti = c_TI[t], tj = c_TJ[t];
    const int i0 = ti * 64, j0 = tj * 64;
    const int kbase = blockIdx.y * 1024;
    const int bz = blockIdx.z;
    const float* X = x + (size_t)bz * C_IN * NSP;

    __shared__ uint32_t As[64 * 36];
    __shared__ uint32_t Bs[64 * 36];

    const int tid = threadIdx.x;
    const int lane = tid & 31, warp = tid >> 5;
    const int wm = warp >> 2, wn = warp & 3;   // warp grid 2 x 4
    const int lr = tid >> 3;                    // 0..31
    const int lc = (tid & 7) * 4;               // 0..28
    const int gq = lane >> 2, tg = lane & 3;    // frag row group / col group

    float acc[2][2][4] = {};
    float s0 = 0.f, s1 = 0.f;
    const bool do_s = (tj == 0);

    for (int k0 = 0; k0 < 1024; k0 += 32) {
        const float* ap0 = X + (size_t)(i0 + lr) * NSP + kbase + k0 + lc;
        const float* ap1 = X + (size_t)(i0 + lr + 32) * NSP + kbase + k0 + lc;
        const float* bp0 = X + (size_t)(j0 + lr) * NSP + kbase + k0 + lc;
        const float* bp1 = X + (size_t)(j0 + lr + 32) * NSP + kbase + k0 + lc;
        float4 va0 = *(const float4*)ap0;
        float4 va1 = *(const float4*)ap1;
        float4 vb0 = *(const float4*)bp0;
        float4 vb1 = *(const float4*)bp1;
        if (do_s) {
            s0 += va0.x + va0.y + va0.z + va0.w;
            s1 += va1.x + va1.y + va1.z + va1.w;
        }
        __syncthreads();
        *(uint4*)&As[lr * 36 + lc] = make_uint4(f2tf32(va0.x), f2tf32(va0.y), f2tf32(va0.z), f2tf32(va0.w));
        *(uint4*)&As[(lr + 32) * 36 + lc] = make_uint4(f2tf32(va1.x), f2tf32(va1.y), f2tf32(va1.z), f2tf32(va1.w));
        *(uint4*)&Bs[lr * 36 + lc] = make_uint4(f2tf32(vb0.x), f2tf32(vb0.y), f2tf32(vb0.z), f2tf32(vb0.w));
        *(uint4*)&Bs[(lr + 32) * 36 + lc] = make_uint4(f2tf32(vb1.x), f2tf32(vb1.y), f2tf32(vb1.z), f2tf32(vb1.w));
        __syncthreads();
#pragma unroll
        for (int kk = 0; kk < 32; kk += 8) {
            uint32_t a[2][4], b[2][2];
#pragma unroll
            for (int ma = 0; ma < 2; ma++) {
                int rb = wm * 32 + ma * 16 + gq;
                a[ma][0] = As[rb * 36 + kk + tg];
                a[ma][1] = As[(rb + 8) * 36 + kk + tg];
                a[ma][2] = As[rb * 36 + kk + 4 + tg];
                a[ma][3] = As[(rb + 8) * 36 + kk + 4 + tg];
            }
#pragma unroll
            for (int na = 0; na < 2; na++) {
                int cb = wn * 16 + na * 8 + gq;
                b[na][0] = Bs[cb * 36 + kk + tg];
                b[na][1] = Bs[cb * 36 + kk + 4 + tg];
            }
#pragma unroll
            for (int ma = 0; ma < 2; ma++)
#pragma unroll
                for (int na = 0; na < 2; na++)
                    mma_tf32(acc[ma][na], a[ma][0], a[ma][1], a[ma][2], a[ma][3],
                             b[na][0], b[na][1]);
        }
    }

    float* Gp = d_G + (size_t)bz * C_IN * C_IN;
#pragma unroll
    for (int ma = 0; ma < 2; ma++) {
        int rr = i0 + wm * 32 + ma * 16 + gq;
#pragma unroll
        for (int na = 0; na < 2; na++) {
            int cn = j0 + wn * 16 + na * 8 + 2 * tg;
            atomicAdd(&Gp[(size_t)rr * 256 + cn],           acc[ma][na][0]);
            atomicAdd(&Gp[(size_t)rr * 256 + cn + 1],       acc[ma][na][1]);
            atomicAdd(&Gp[(size_t)(rr + 8) * 256 + cn],     acc[ma][na][2]);
            atomicAdd(&Gp[(size_t)(rr + 8) * 256 + cn + 1], acc[ma][na][3]);
            if (ti != tj) {
                atomicAdd(&Gp[(size_t)cn * 256 + rr],           acc[ma][na][0]);
                atomicAdd(&Gp[(size_t)(cn + 1) * 256 + rr],     acc[ma][na][1]);
                atomicAdd(&Gp[(size_t)cn * 256 + rr + 8],       acc[ma][na][2]);
                atomicAdd(&Gp[(size_t)(cn + 1) * 256 + rr + 8], acc[ma][na][3]);
            }
        }
    }
    if (do_s) {
        atomicAdd(&d_s[bz * C_IN + i0 + lr], s0);
        atomicAdd(&d_s[bz * C_IN + i0 + lr + 32], s1);
    }
}

// ---------------------------------------------------------------------------
// bv1: per-batch independent warp-dots: ws (128), up (256), Gq (256), beta.
// beta = s.q  (since ws.theta_b == s.(phi_w^T theta_b) == s.q)
// grid (81, BATCH), block 256 (8 warps, 1 task each)
// ---------------------------------------------------------------------------
__global__ void __launch_bounds__(256) bv1(const float* __restrict__ phi_w) {
    const int bz = blockIdx.y;
    const int tid = threadIdx.x, warp = tid >> 5, lane = tid & 31;
    const int task = blockIdx.x * 8 + warp;       // 0..640

    __shared__ float sv[C_IN], qs[C_IN];
    if (tid < C_IN) {
        sv[tid] = d_s[bz * C_IN + tid];
        qs[tid] = d_q[tid];
    }
    __syncthreads();

    if (task < 128) {
        // ws[task] = phi_w[task,:] . s
        float v = warp_dot256(phi_w + task * C_IN, sv);
        if (lane == 0) d_ws[bz * C_MID + task] = v;
    } else if (task < 384) {
        int r = task - 128;
        float v = warp_dot256(d_OG + r * C_IN, sv);
        if (lane == 0) d_up[bz * C_IN + r] = v * INVN;
    } else if (task < 640) {
        int r = task - 384;
        float v = warp_dot256(d_G + (size_t)bz * C_IN * C_IN + r * C_IN, qs);
        if (lane == 0) d_Gq[bz * C_IN + r] = v;
    } else {
        // beta = s . q
        float a = sv[lane] * qs[lane] + sv[lane + 32] * qs[lane + 32]
                + sv[lane + 64] * qs[lane + 64] + sv[lane + 96] * qs[lane + 96]
                + sv[lane + 128] * qs[lane + 128] + sv[lane + 160] * qs[lane + 160]
                + sv[lane + 192] * qs[lane + 192] + sv[lane + 224] * qs[lane + 224];
#pragma unroll
        for (int o = 16; o; o >>= 1) a += __shfl_xor_sync(0xffffffffu, a, o);
        if (lane == 0) d_beta[bz] = a;
    }
}

// ---------------------------------------------------------------------------
// bv2: vp (block x==0) and cvec (blocks 1..8), grid (9, BATCH)
// ---------------------------------------------------------------------------
__global__ void __launch_bounds__(256) bv2(const float* __restrict__ theta_w,
                                           const float* __restrict__ out_b) {
    const int bz = blockIdx.y;
    const int tid = threadIdx.x, warp = tid >> 5, lane = tid & 31;

    if (blockIdx.x == 0) {
        // vp[j] = (theta_w^T ws)[j]/N + tp[j]
        __shared__ float ws[C_MID];
        if (tid < C_MID) ws[tid] = d_ws[bz * C_MID + tid];
        __syncthreads();
        float a = 0.f;
#pragma unroll 8
        for (int k = 0; k < C_MID; k++) a += theta_w[k * C_IN + tid] * ws[k];
        d_vp[bz * C_IN + tid] = a * INVN + d_tp[tid];
    } else {
        // cvec[r] = (OG[r,:].Gq)/N + alpha*up[r] + (beta/N+alpha)*og[r] + out_b[r]
        __shared__ float Gq[C_IN];
        if (tid < C_IN) Gq[tid] = d_Gq[bz * C_IN + tid];
        __syncthreads();
        const float alpha = d_alpha;
        const float bcoef = d_beta[bz] * INVN + alpha;
        int r = (blockIdx.x - 1) * 32 + warp * 4;
#pragma unroll
        for (int i = 0; i < 4; i++, r++) {
            float tv = warp_dot256(d_OG + r * C_IN, Gq);
            if (lane == 0)
                d_cvec[bz * C_IN + r] = tv * INVN + alpha * d_up[bz * C_IN + r] +
                                        bcoef * d_og[r] + out_b[r];
        }
    }
}

// ---------------------------------------------------------------------------
// Final GEMM via tf32 tensor cores: out = Afold @ X + X + c
// grid (32 n-tiles of 128, 4 m-tiles of 64, 4 batch), block 256 (2m x 4n warps)
// ---------------------------------------------------------------------------
__global__ void __launch_bounds__(256) final_tc(const float* __restrict__ x,
                                                float* __restrict__ out) {
    const int n0 = blockIdx.x * 128;
    const int m0 = blockIdx.y * 64;
    const int bz = blockIdx.z;
    const float* Ab = d_Afold + (size_t)bz * C_IN * C_IN;
    const float* Xb = x + (size_t)bz * C_IN * NSP;
    float* Ob = out + (size_t)bz * C_IN * NSP;

    __shared__ uint32_t As[64 * 36];
    __shared__ uint32_t Bs[32 * 136];

    const int tid = threadIdx.x;
    const int lane = tid & 31, warp = tid >> 5;
    const int wm = warp >> 2, wn = warp & 3;    // 2 x 4 warps
    const int gq = lane >> 2, tg = lane & 3;

    const int alr = tid >> 3;                  // 0..31 (rows alr, alr+32)
    const int alc = (tid & 7) * 4;
    const int blr = tid >> 3;
    const int bf4 = (tid & 7);

    float acc[2][4][4] = {};

    for (int k0 = 0; k0 < 256; k0 += 32) {
        float4 va0 = *(const float4*)(Ab + (size_t)(m0 + alr) * 256 + k0 + alc);
        float4 va1 = *(const float4*)(Ab + (size_t)(m0 + alr + 32) * 256 + k0 + alc);
        float4 vb[4];
#pragma unroll
        for (int i = 0; i < 4; i++) {
            int fc = (bf4 + 8 * i) * 4;
            vb[i] = *(const float4*)(Xb + (size_t)(k0 + blr) * NSP + n0 + fc);
        }
        __syncthreads();
        *(uint4*)&As[alr * 36 + alc] = make_uint4(f2tf32(va0.x), f2tf32(va0.y), f2tf32(va0.z), f2tf32(va0.w));
        *(uint4*)&As[(alr + 32) * 36 + alc] = make_uint4(f2tf32(va1.x), f2tf32(va1.y), f2tf32(va1.z), f2tf32(va1.w));
#pragma unroll
        for (int i = 0; i < 4; i++) {
            int fc = (bf4 + 8 * i) * 4;
            *(uint4*)&Bs[blr * 136 + fc] = make_uint4(f2tf32(vb[i].x), f2tf32(vb[i].y), f2tf32(vb[i].z), f2tf32(vb[i].w));
        }
        __syncthreads();
#pragma unroll
        for (int kk = 0; kk < 32; kk += 8) {
            uint32_t a[2][4], b[4][2];
#pragma unroll
            for (int ma = 0; ma < 2; ma++) {
                int rb = wm * 32 + ma * 16 + gq;
                a[ma][0] = As[rb * 36 + kk + tg];
                a[ma][1] = As[(rb + 8) * 36 + kk + tg];
                a[ma][2] = As[rb * 36 + kk + 4 + tg];
                a[ma][3] = As[(rb + 8) * 36 + kk + 4 + tg];
            }
#pragma unroll
            for (int na = 0; na < 4; na++) {
                int cb = wn * 32 + na * 8 + gq;
                b[na][0] = Bs[(kk + tg) * 136 + cb];
                b[na][1] = Bs[(kk + 4 + tg) * 136 + cb];
            }
#pragma unroll
            for (int ma = 0; ma < 2; ma++)
#pragma unroll
                for (int na = 0; na < 4; na++)
                    mma_tf32(acc[ma][na], a[ma][0], a[ma][1], a[ma][2], a[ma][3],
                             b[na][0], b[na][1]);
        }
    }

    // Epilogue: + X + c, write out
    const float* cb = d_cvec + bz * C_IN;
#pragma unroll
    for (int ma = 0; ma < 2; ma++) {
        int rm = m0 + wm * 32 + ma * 16 + gq;
        float ci0 = cb[rm], ci1 = cb[rm + 8];
#pragma unroll
        for (int na = 0; na < 4; na++) {
            int cn = n0 + wn * 32 + na * 8 + 2 * tg;
            float2 x0 = *(const float2*)(Xb + (size_t)rm * NSP + cn);
            float2 x1 = *(const float2*)(Xb + (size_t)(rm + 8) * NSP + cn);
            float2 o0 = make_float2(acc[ma][na][0] + x0.x + ci0, acc[ma][na][1] + x0.y + ci0);
            float2 o1 = make_float2(acc[ma][na][2] + x1.x + ci1, acc[ma][na][3] + x1.y + ci1);
            *(float2*)(Ob + (size_t)rm * NSP + cn) = o0;
            *(float2*)(Ob + (size_t)(rm + 8) * NSP + cn) = o1;
        }
    }
}

// ---------------------------------------------------------------------------
// Host launcher
// ---------------------------------------------------------------------------
extern "C" void kernel_launch(void* const* d_in, const int* in_sizes, int n_in,
                              void* d_out, int out_size) {
    const float* x       = (const float*)d_in[0];
    const float* g_w     = (const float*)d_in[1];
    const float* g_b     = (const float*)d_in[2];
    const float* theta_w = (const float*)d_in[3];
    const float* theta_b = (const float*)d_in[4];
    const float* phi_w   = (const float*)d_in[5];
    const float* phi_b   = (const float*)d_in[6];
    const float* out_w   = (const float*)d_in[7];
    const float* out_b   = (const float*)d_in[8];
    float* out = (float*)d_out;

    float *pG, *pU, *pA, *pOG, *pPT;
    cudaGetSymbolAddress((void**)&pG, d_G);
    cudaGetSymbolAddress((void**)&pU, d_U);
    cudaGetSymbolAddress((void**)&pA, d_Afold);
    cudaGetSymbolAddress((void**)&pOG, d_OG);
    cudaGetSymbolAddress((void**)&pPT, d_PT);

    const long CC = (long)C_IN * C_IN;

    // 1) zero G/s + batch-independent vectors
    setup_misc<<<64, 256>>>(out_w, g_b, theta_w, phi_b, phi_w, theta_b);
    // 2) OG = out_w @ g_w ; PT = phi_w^T @ theta_w
    wgemm_small<<<dim3(8, 8, 2), 256>>>(out_w, g_w, phi_w, theta_w);
    // 3) Gram (tensor cores, triangle + mirror, split-K) + row sums
    gram_tc<<<dim3(10, 4, BATCH), 256>>>(x);
    // 4) per-batch vectors phase 1 (ws, up, Gq, beta) — massively parallel
    bv1<<<dim3(81, BATCH), 256>>>(phi_w);
    // 5) per-batch vectors phase 2 (vp, cvec)
    bv2<<<dim3(9, BATCH), 256>>>(theta_w, out_b);
    // 6) U_b = OG @ G_b
    gemm32k<0><<<dim3(8, 8, BATCH), 256>>>(pOG, pG, pU, 256, 0, CC, CC);
    // 7) A_b = (U_b @ PT)/N + up⊗tp + og⊗vp
    gemm32k<1><<<dim3(8, 8, BATCH), 256>>>(pU, pPT, pA, 256, CC, 0, CC);
    // 8) out_b = A_b @ X_b + X_b + c_b  (tensor cores)
    final_tc<<<dim3(32, 4, BATCH), 256>>>(x, out);
}

// round 4
// speedup vs baseline: 2.7336x; 1.0899x over previous
#include <cuda_runtime.h>
#include <cuda_bf16.h>
#include <cstdint>

#define BATCH 4
#define C_IN 256
#define C_MID 128
#define NSP 4096
#define INVN (1.0f/4096.0f)
#define CC (C_IN * C_IN)

// ---------------------------------------------------------------------------
// Device scratch
// ---------------------------------------------------------------------------
__device__ __align__(256) float d_G[BATCH * CC];
__device__ __align__(256) float d_s[BATCH * C_IN];
__device__ __align__(256) float d_U[BATCH * CC];
__device__ __align__(256) float d_Afold[BATCH * CC];
__device__ __align__(256) float d_OG[CC];
__device__ __align__(256) float d_PT[CC];
__device__ __align__(256) float d_og[C_IN];
__device__ __align__(256) float d_tp[C_IN];
__device__ __align__(256) float d_q[C_IN];
__device__ __align__(256) float d_up[BATCH * C_IN];
__device__ __align__(256) float d_vp[BATCH * C_IN];
__device__ __align__(256) float d_cvec[BATCH * C_IN];
__device__ __align__(256) float d_Gq[BATCH * C_IN];
__device__ __align__(256) float d_beta[BATCH];
__device__ float d_alpha;

__constant__ unsigned char c_TI[10] = {0,1,1,2,2,2,3,3,3,3};
__constant__ unsigned char c_TJ[10] = {0,0,1,0,1,2,0,1,2,3};

// ---------------------------------------------------------------------------
// Helpers
// ---------------------------------------------------------------------------
__device__ __forceinline__ void mma_tf32(float c[4],
                                         uint32_t a0, uint32_t a1, uint32_t a2, uint32_t a3,
                                         uint32_t b0, uint32_t b1) {
    asm volatile("mma.sync.aligned.m16n8k8.row.col.f32.tf32.tf32.f32 "
                 "{%0,%1,%2,%3}, {%4,%5,%6,%7}, {%8,%9}, {%0,%1,%2,%3};"
                 : "+f"(c[0]), "+f"(c[1]), "+f"(c[2]), "+f"(c[3])
                 : "r"(a0), "r"(a1), "r"(a2), "r"(a3), "r"(b0), "r"(b1));
}

__device__ __forceinline__ uint32_t fbits(float f) { return __float_as_uint(f); }

__device__ __forceinline__ float warp_dot(const float* __restrict__ row,
                                          const float* __restrict__ v, int K) {
    int lane = threadIdx.x & 31;
    float a = 0.f;
    for (int k = lane; k < K; k += 32) a += row[k] * v[k];
#pragma unroll
    for (int o = 16; o; o >>= 1) a += __shfl_xor_sync(0xffffffffu, a, o);
    return a;
}

__device__ __forceinline__ float warp_dot256(const float* __restrict__ row,
                                             const float* __restrict__ v) {
    int lane = threadIdx.x & 31;
    float4 r0 = *(const float4*)(row + lane * 4);
    float4 r1 = *(const float4*)(row + 128 + lane * 4);
    float4 v0 = *(const float4*)(v + lane * 4);
    float4 v1 = *(const float4*)(v + 128 + lane * 4);
    float a = r0.x * v0.x + r0.y * v0.y + r0.z * v0.z + r0.w * v0.w
            + r1.x * v1.x + r1.y * v1.y + r1.z * v1.z + r1.w * v1.w;
#pragma unroll
    for (int o = 16; o; o >>= 1) a += __shfl_xor_sync(0xffffffffu, a, o);
    return a;
}

// ---------------------------------------------------------------------------
// SIMT 32x32 GEMM body for the two tiny K=128 weight GEMMs (inside prep)
// ---------------------------------------------------------------------------
__device__ __forceinline__ void gemm32_body(const float* __restrict__ A, int lda, bool atrans,
                                            const float* __restrict__ B,
                                            float* __restrict__ C, int K, int i0, int j0) {
    __shared__ float As[32][33];
    __shared__ float Bs[32][33];
    const int tid = threadIdx.x;
    const int tx = tid & 15, ty = tid >> 4;
    const int lr = tid >> 3, lc = (tid & 7) * 4;

    float a00 = 0.f, a01 = 0.f, a10 = 0.f, a11 = 0.f;

    for (int k0 = 0; k0 < K; k0 += 32) {
        float4 va;
        if (!atrans) va = *(const float4*)(A + (size_t)(i0 + lr) * lda + k0 + lc);
        else         va = *(const float4*)(A + (size_t)(k0 + lr) * lda + i0 + lc);
        float4 vb = *(const float4*)(B + (size_t)(k0 + lr) * 256 + j0 + lc);
        __syncthreads();
        if (!atrans) {
            As[lc + 0][lr] = va.x; As[lc + 1][lr] = va.y;
            As[lc + 2][lr] = va.z; As[lc + 3][lr] = va.w;
        } else {
            As[lr][lc + 0] = va.x; As[lr][lc + 1] = va.y;
            As[lr][lc + 2] = va.z; As[lr][lc + 3] = va.w;
        }
        Bs[lr][lc + 0] = vb.x; Bs[lr][lc + 1] = vb.y;
        Bs[lr][lc + 2] = vb.z; Bs[lr][lc + 3] = vb.w;
        __syncthreads();
#pragma unroll
        for (int k = 0; k < 32; k++) {
            float av0 = As[k][ty * 2], av1 = As[k][ty * 2 + 1];
            float bv0 = Bs[k][tx * 2], bv1 = Bs[k][tx * 2 + 1];
            a00 += av0 * bv0; a01 += av0 * bv1;
            a10 += av1 * bv0; a11 += av1 * bv1;
        }
    }
    const int i = i0 + ty * 2, j = j0 + tx * 2;
    C[(size_t)i * 256 + j] = a00;       C[(size_t)i * 256 + j + 1] = a01;
    C[(size_t)(i + 1) * 256 + j] = a10; C[(size_t)(i + 1) * 256 + j + 1] = a11;
}

// ---------------------------------------------------------------------------
// prep: blocks 0..63 OG tiles, 64..127 PT tiles, 128..191 zero G/s, 192 vectors
// ---------------------------------------------------------------------------
__global__ void __launch_bounds__(256) prep(const float* __restrict__ out_w,
                                            const float* __restrict__ g_w,
                                            const float* __restrict__ phi_w,
                                            const float* __restrict__ theta_w,
                                            const float* __restrict__ g_b,
                                            const float* __restrict__ phi_b,
                                            const float* __restrict__ theta_b) {
    const int b = blockIdx.x;
    const int tid = threadIdx.x;
    if (b < 64) {
        gemm32_body(out_w, C_MID, false, g_w, d_OG, C_MID, (b >> 3) * 32, (b & 7) * 32);
    } else if (b < 128) {
        int t = b - 64;
        gemm32_body(phi_w, C_IN, true, theta_w, d_PT, C_MID, (t >> 3) * 32, (t & 7) * 32);
    } else if (b < 192) {
        int bi = b - 128;
        for (int idx = bi * 256 + tid; idx < BATCH * CC; idx += 64 * 256)
            d_G[idx] = 0.f;
        if (bi == 0 && tid < BATCH * C_IN / 4) ((float4*)d_s)[tid] = make_float4(0, 0, 0, 0);
    } else {
        const int wid = tid >> 5, lane = tid & 31;
        for (int r = wid; r < C_IN; r += 8) {
            float v = warp_dot(out_w + r * C_MID, g_b, C_MID);
            if (lane == 0) d_og[r] = v;
        }
        float a = 0.f, bb = 0.f;
        for (int k = 0; k < C_MID; k++) {
            a += theta_w[k * C_IN + tid] * phi_b[k];
            bb += phi_w[k * C_IN + tid] * theta_b[k];
        }
        d_tp[tid] = a;
        d_q[tid] = bb;
        if (wid == 0) {
            float al = 0.f;
            for (int k = lane; k < C_MID; k += 32) al += phi_b[k] * theta_b[k];
#pragma unroll
            for (int o = 16; o; o >>= 1) al += __shfl_xor_sync(0xffffffffu, al, o);
            if (lane == 0) d_alpha = al;
        }
    }
}

// ---------------------------------------------------------------------------
// Gram via tf32 TC (raw fp32 bits). triangle+mirror, split-K=4, + row sums.
// ---------------------------------------------------------------------------
__global__ void __launch_bounds__(256) gram_tc(const float* __restrict__ x) {
    const int t = blockIdx.x;
    const int ti = c_TI[t], tj = c_TJ[t];
    const int i0 = ti * 64, j0 = tj * 64;
    const int kbase = blockIdx.y * 1024;
    const int bz = blockIdx.z;
    const float* X = x + (size_t)bz * C_IN * NSP;

    __shared__ float As[64 * 36];
    __shared__ float Bs[64 * 36];

    const int tid = threadIdx.x;
    const int lane = tid & 31, warp = tid >> 5;
    const int wm = warp >> 2, wn = warp & 3;
    const int lr = tid >> 3;
    const int lc = (tid & 7) * 4;
    const int gq = lane >> 2, tg = lane & 3;

    float acc[2][2][4] = {};
    float s0 = 0.f, s1 = 0.f;
    const bool do_s = (tj == 0);

    for (int k0 = 0; k0 < 1024; k0 += 32) {
        float4 va0 = *(const float4*)(X + (size_t)(i0 + lr) * NSP + kbase + k0 + lc);
        float4 va1 = *(const float4*)(X + (size_t)(i0 + lr + 32) * NSP + kbase + k0 + lc);
        float4 vb0 = *(const float4*)(X + (size_t)(j0 + lr) * NSP + kbase + k0 + lc);
        float4 vb1 = *(const float4*)(X + (size_t)(j0 + lr + 32) * NSP + kbase + k0 + lc);
        if (do_s) {
            s0 += va0.x + va0.y + va0.z + va0.w;
            s1 += va1.x + va1.y + va1.z + va1.w;
        }
        __syncthreads();
        *(float4*)&As[lr * 36 + lc] = va0;
        *(float4*)&As[(lr + 32) * 36 + lc] = va1;
        *(float4*)&Bs[lr * 36 + lc] = vb0;
        *(float4*)&Bs[(lr + 32) * 36 + lc] = vb1;
        __syncthreads();
#pragma unroll
        for (int kk = 0; kk < 32; kk += 8) {
            uint32_t a[2][4], b[2][2];
#pragma unroll
            for (int ma = 0; ma < 2; ma++) {
                int rb = wm * 32 + ma * 16 + gq;
                a[ma][0] = fbits(As[rb * 36 + kk + tg]);
                a[ma][1] = fbits(As[(rb + 8) * 36 + kk + tg]);
                a[ma][2] = fbits(As[rb * 36 + kk + 4 + tg]);
                a[ma][3] = fbits(As[(rb + 8) * 36 + kk + 4 + tg]);
            }
#pragma unroll
            for (int na = 0; na < 2; na++) {
                int cb = wn * 16 + na * 8 + gq;
                b[na][0] = fbits(Bs[cb * 36 + kk + tg]);
                b[na][1] = fbits(Bs[cb * 36 + kk + 4 + tg]);
            }
#pragma unroll
            for (int ma = 0; ma < 2; ma++)
#pragma unroll
                for (int na = 0; na < 2; na++)
                    mma_tf32(acc[ma][na], a[ma][0], a[ma][1], a[ma][2], a[ma][3],
                             b[na][0], b[na][1]);
        }
    }

    float* Gp = d_G + (size_t)bz * CC;
#pragma unroll
    for (int ma = 0; ma < 2; ma++) {
        int rr = i0 + wm * 32 + ma * 16 + gq;
#pragma unroll
        for (int na = 0; na < 2; na++) {
            int cn = j0 + wn * 16 + na * 8 + 2 * tg;
            atomicAdd(&Gp[(size_t)rr * 256 + cn],           acc[ma][na][0]);
            atomicAdd(&Gp[(size_t)rr * 256 + cn + 1],       acc[ma][na][1]);
            atomicAdd(&Gp[(size_t)(rr + 8) * 256 + cn],     acc[ma][na][2]);
            atomicAdd(&Gp[(size_t)(rr + 8) * 256 + cn + 1], acc[ma][na][3]);
            if (ti != tj) {
                atomicAdd(&Gp[(size_t)cn * 256 + rr],           acc[ma][na][0]);
                atomicAdd(&Gp[(size_t)(cn + 1) * 256 + rr],     acc[ma][na][1]);
                atomicAdd(&Gp[(size_t)cn * 256 + rr + 8],       acc[ma][na][2]);
                atomicAdd(&Gp[(size_t)(cn + 1) * 256 + rr + 8], acc[ma][na][3]);
            }
        }
    }
    if (do_s) {
        atomicAdd(&d_s[bz * C_IN + i0 + lr], s0);
        atomicAdd(&d_s[bz * C_IN + i0 + lr + 32], s1);
    }
}

// ---------------------------------------------------------------------------
// TC 64x64x256 GEMM body (tf32, raw bits). MODE 0: C=A@B.
// MODE 1: C=A@B*INVN + up[i]*tp[j] + og[i]*vp[j]
// ---------------------------------------------------------------------------
template <int MODE>
__device__ __forceinline__ void tc64(const float* __restrict__ A,
                                     const float* __restrict__ B,
                                     float* __restrict__ C,
                                     int i0, int j0, int bz, float* sm) {
    float* As = sm;              // 64*36
    float* Bs = sm + 64 * 36;    // 32*68
    const int tid = threadIdx.x;
    const int lane = tid & 31, warp = tid >> 5;
    const int wm = warp >> 2, wn = warp & 3;
    const int gq = lane >> 2, tg = lane & 3;
    const int lr = tid >> 3, lc = (tid & 7) * 4;
    const int bk = tid >> 4, bn = (tid & 15) * 4;

    float acc[2][2][4] = {};

    for (int k0 = 0; k0 < 256; k0 += 32) {
        float4 va0 = *(const float4*)(A + (size_t)(i0 + lr) * 256 + k0 + lc);
        float4 va1 = *(const float4*)(A + (size_t)(i0 + lr + 32) * 256 + k0 + lc);
        float4 vb0 = *(const float4*)(B + (size_t)(k0 + bk) * 256 + j0 + bn);
        float4 vb1 = *(const float4*)(B + (size_t)(k0 + bk + 16) * 256 + j0 + bn);
        __syncthreads();
        *(float4*)&As[lr * 36 + lc] = va0;
        *(float4*)&As[(lr + 32) * 36 + lc] = va1;
        *(float4*)&Bs[bk * 68 + bn] = vb0;
        *(float4*)&Bs[(bk + 16) * 68 + bn] = vb1;
        __syncthreads();
#pragma unroll
        for (int kk = 0; kk < 32; kk += 8) {
            uint32_t a[2][4], b[2][2];
#pragma unroll
            for (int ma = 0; ma < 2; ma++) {
                int rb = wm * 32 + ma * 16 + gq;
                a[ma][0] = fbits(As[rb * 36 + kk + tg]);
                a[ma][1] = fbits(As[(rb + 8) * 36 + kk + tg]);
                a[ma][2] = fbits(As[rb * 36 + kk + 4 + tg]);
                a[ma][3] = fbits(As[(rb + 8) * 36 + kk + 4 + tg]);
            }
#pragma unroll
            for (int na = 0; na < 2; na++) {
                int cb = wn * 16 + na * 8 + gq;
                b[na][0] = fbits(Bs[(kk + tg) * 68 + cb]);
                b[na][1] = fbits(Bs[(kk + 4 + tg) * 68 + cb]);
            }
#pragma unroll
            for (int ma = 0; ma < 2; ma++)
#pragma unroll
                for (int na = 0; na < 2; na++)
                    mma_tf32(acc[ma][na], a[ma][0], a[ma][1], a[ma][2], a[ma][3],
                             b[na][0], b[na][1]);
        }
    }

#pragma unroll
    for (int ma = 0; ma < 2; ma++) {
        int rm = i0 + wm * 32 + ma * 16 + gq;
#pragma unroll
        for (int na = 0; na < 2; na++) {
            int cn = j0 + wn * 16 + na * 8 + 2 * tg;
            if (MODE == 0) {
                *(float2*)(C + (size_t)rm * 256 + cn)       = make_float2(acc[ma][na][0], acc[ma][na][1]);
                *(float2*)(C + (size_t)(rm + 8) * 256 + cn) = make_float2(acc[ma][na][2], acc[ma][na][3]);
            } else {
                const float* ub = d_up + bz * C_IN;
                const float* vb = d_vp + bz * C_IN;
                float u0 = ub[rm], u1 = ub[rm + 8], o0 = d_og[rm], o1 = d_og[rm + 8];
                float t0 = d_tp[cn], t1 = d_tp[cn + 1];
                float v0 = vb[cn], v1 = vb[cn + 1];
                *(float2*)(C + (size_t)rm * 256 + cn) = make_float2(
                    acc[ma][na][0] * INVN + u0 * t0 + o0 * v0,
                    acc[ma][na][1] * INVN + u0 * t1 + o0 * v1);
                *(float2*)(C + (size_t)(rm + 8) * 256 + cn) = make_float2(
                    acc[ma][na][2] * INVN + u1 * t0 + o1 * v0,
                    acc[ma][na][3] * INVN + u1 * t1 + o1 * v1);
            }
        }
    }
}

// ---------------------------------------------------------------------------
// mid: blocks 0..63: U_b = OG @ G_b (TC). 64..67: vp + beta. 68..99: up, Gq.
// ---------------------------------------------------------------------------
__global__ void __launch_bounds__(256) mid() {
    __shared__ float sm[64 * 36 + 32 * 68];
    const int b = blockIdx.x;
    const int tid = threadIdx.x, warp = tid >> 5, lane = tid & 31;

    if (b < 64) {
        int bz = b >> 4, t = b & 15;
        tc64<0>(d_OG, d_G + (size_t)bz * CC, d_U + (size_t)bz * CC,
                (t >> 2) * 64, (t & 3) * 64, bz, sm);
    } else if (b < 68) {
        int bz = b - 64;
        float* sv = sm;
        float* qv = sm + 256;
        sv[tid] = d_s[bz * C_IN + tid];
        qv[tid] = d_q[tid];
        __syncthreads();
        // vp[j] = (PT^T s)[j]/N + tp[j]
        float a = 0.f;
#pragma unroll 4
        for (int i = 0; i < C_IN; i++) a += d_PT[(size_t)i * 256 + tid] * sv[i];
        d_vp[bz * C_IN + tid] = a * INVN + d_tp[tid];
        // beta = s . q
        if (warp == 0) {
            float bt = 0.f;
#pragma unroll
            for (int k = 0; k < 8; k++) bt += sv[lane + k * 32] * qv[lane + k * 32];
#pragma unroll
            for (int o = 16; o; o >>= 1) bt += __shfl_xor_sync(0xffffffffu, bt, o);
            if (lane == 0) d_beta[bz] = bt;
        }
    } else {
        int rb = b - 68;
        int bz = rb >> 3, sub = rb & 7;
        float* sv = sm;
        float* qv = sm + 256;
        sv[tid] = d_s[bz * C_IN + tid];
        qv[tid] = d_q[tid];
        __syncthreads();
        if (sub < 4) {
            int r = sub * 64 + warp * 8;
#pragma unroll
            for (int d = 0; d < 8; d++) {
                float v = warp_dot256(d_OG + (size_t)(r + d) * 256, sv);
                if (lane == 0) d_up[bz * C_IN + r + d] = v * INVN;
            }
        } else {
            int r = (sub - 4) * 64 + warp * 8;
#pragma unroll
            for (int d = 0; d < 8; d++) {
                float v = warp_dot256(d_G + (size_t)bz * CC + (size_t)(r + d) * 256, qv);
                if (lane == 0) d_Gq[bz * C_IN + r + d] = v;
            }
        }
    }
}

// ---------------------------------------------------------------------------
// amid: blocks 0..63: A_b = U_b@PT*INVN + rank-1 (TC). 64..95: cvec.
// ---------------------------------------------------------------------------
__global__ void __launch_bounds__(256) amid(const float* __restrict__ out_b) {
    __shared__ float sm[64 * 36 + 32 * 68];
    const int b = blockIdx.x;
    const int tid = threadIdx.x, warp = tid >> 5, lane = tid & 31;

    if (b < 64) {
        int bz = b >> 4, t = b & 15;
        tc64<1>(d_U + (size_t)bz * CC, d_PT, d_Afold + (size_t)bz * CC,
                (t >> 2) * 64, (t & 3) * 64, bz, sm);
    } else {
        int rb = b - 64;
        int bz = rb >> 3, sub = rb & 7;
        float* Gqs = sm;
        Gqs[tid] = d_Gq[bz * C_IN + tid];
        __syncthreads();
        const float alpha = d_alpha;
        const float bcoef = d_beta[bz] * INVN + alpha;
        int r = sub * 32 + warp * 4;
#pragma unroll
        for (int i = 0; i < 4; i++) {
            float tv = warp_dot256(d_OG + (size_t)(r + i) * 256, Gqs);
            if (lane == 0)
                d_cvec[bz * C_IN + r + i] = tv * INVN + alpha * d_up[bz * C_IN + r + i] +
                                            bcoef * d_og[r + i] + out_b[r + i];
        }
    }
}

// ---------------------------------------------------------------------------
// final: out = Afold @ X + X + c (TC, raw bits)
// ---------------------------------------------------------------------------
__global__ void __launch_bounds__(256) final_tc(const float* __restrict__ x,
                                                float* __restrict__ out) {
    const int n0 = blockIdx.x * 128;
    const int m0 = blockIdx.y * 64;
    const int bz = blockIdx.z;
    const float* Ab = d_Afold + (size_t)bz * CC;
    const float* Xb = x + (size_t)bz * C_IN * NSP;
    float* Ob = out + (size_t)bz * C_IN * NSP;

    __shared__ float As[64 * 36];
    __shared__ float Bs[32 * 136];

    const int tid = threadIdx.x;
    const int lane = tid & 31, warp = tid >> 5;
    const int wm = warp >> 2, wn = warp & 3;
    const int gq = lane >> 2, tg = lane & 3;
    const int alr = tid >> 3, alc = (tid & 7) * 4;
    const int blr = tid >> 3, bf4 = (tid & 7);

    float acc[2][4][4] = {};

    for (int k0 = 0; k0 < 256; k0 += 32) {
        float4 va0 = *(const float4*)(Ab + (size_t)(m0 + alr) * 256 + k0 + alc);
        float4 va1 = *(const float4*)(Ab + (size_t)(m0 + alr + 32) * 256 + k0 + alc);
        float4 vb[4];
#pragma unroll
        for (int i = 0; i < 4; i++)
            vb[i] = *(const float4*)(Xb + (size_t)(k0 + blr) * NSP + n0 + (bf4 + 8 * i) * 4);
        __syncthreads();
        *(float4*)&As[alr * 36 + alc] = va0;
        *(float4*)&As[(alr + 32) * 36 + alc] = va1;
#pragma unroll
        for (int i = 0; i < 4; i++)
            *(float4*)&Bs[blr * 136 + (bf4 + 8 * i) * 4] = vb[i];
        __syncthreads();
#pragma unroll
        for (int kk = 0; kk < 32; kk += 8) {
            uint32_t a[2][4], b[4][2];
#pragma unroll
            for (int ma = 0; ma < 2; ma++) {
                int rb = wm * 32 + ma * 16 + gq;
                a[ma][0] = fbits(As[rb * 36 + kk + tg]);
                a[ma][1] = fbits(As[(rb + 8) * 36 + kk + tg]);
                a[ma][2] = fbits(As[rb * 36 + kk + 4 + tg]);
                a[ma][3] = fbits(As[(rb + 8) * 36 + kk + 4 + tg]);
            }
#pragma unroll
            for (int na = 0; na < 4; na++) {
                int cb = wn * 32 + na * 8 + gq;
                b[na][0] = fbits(Bs[(kk + tg) * 136 + cb]);
                b[na][1] = fbits(Bs[(kk + 4 + tg) * 136 + cb]);
            }
#pragma unroll
            for (int ma = 0; ma < 2; ma++)
#pragma unroll
                for (int na = 0; na < 4; na++)
                    mma_tf32(acc[ma][na], a[ma][0], a[ma][1], a[ma][2], a[ma][3],
                             b[na][0], b[na][1]);
        }
    }

    const float* cb = d_cvec + bz * C_IN;
#pragma unroll
    for (int ma = 0; ma < 2; ma++) {
        int rm = m0 + wm * 32 + ma * 16 + gq;
        float ci0 = cb[rm], ci1 = cb[rm + 8];
#pragma unroll
        for (int na = 0; na < 4; na++) {
            int cn = n0 + wn * 32 + na * 8 + 2 * tg;
            float2 x0 = *(const float2*)(Xb + (size_t)rm * NSP + cn);
            float2 x1 = *(const float2*)(Xb + (size_t)(rm + 8) * NSP + cn);
            *(float2*)(Ob + (size_t)rm * NSP + cn) =
                make_float2(acc[ma][na][0] + x0.x + ci0, acc[ma][na][1] + x0.y + ci0);
            *(float2*)(Ob + (size_t)(rm + 8) * NSP + cn) =
                make_float2(acc[ma][na][2] + x1.x + ci1, acc[ma][na][3] + x1.y + ci1);
        }
    }
}

// ---------------------------------------------------------------------------
// Host launcher — 5 kernels
// ---------------------------------------------------------------------------
extern "C" void kernel_launch(void* const* d_in, const int* in_sizes, int n_in,
                              void* d_out, int out_size) {
    const float* x       = (const float*)d_in[0];
    const float* g_w     = (const float*)d_in[1];
    const float* g_b     = (const float*)d_in[2];
    const float* theta_w = (const float*)d_in[3];
    const float* theta_b = (const float*)d_in[4];
    const float* phi_w   = (const float*)d_in[5];
    const float* phi_b   = (const float*)d_in[6];
    const float* out_w   = (const float*)d_in[7];
    const float* out_b   = (const float*)d_in[8];
    float* out = (float*)d_out;

    prep<<<193, 256>>>(out_w, g_w, phi_w, theta_w, g_b, phi_b, theta_b);
    gram_tc<<<dim3(10, 4, BATCH), 256>>>(x);
    mid<<<100, 256>>>();
    amid<<<96, 256>>>(out_b);
    final_tc<<<dim3(32, 4, BATCH), 256>>>(x, out);
}

// round 5
// speedup vs baseline: 2.9380x; 1.0748x over previous
#include <cuda_runtime.h>
#include <cstdint>

#define BATCH 4
#define C_IN 256
#define C_MID 128
#define NSP 4096
#define INVN (1.0f/4096.0f)
#define CC (C_IN * C_IN)

// ---------------------------------------------------------------------------
// Device scratch
// ---------------------------------------------------------------------------
__device__ __align__(256) float d_G[BATCH * CC];
__device__ __align__(256) float d_s[BATCH * C_IN];
__device__ __align__(256) float d_T1[BATCH * C_MID * NSP];
__device__ __align__(256) float d_T2[BATCH * C_MID * NSP];
__device__ __align__(256) float d_B1[BATCH * C_MID * C_IN];
__device__ __align__(256) float d_Bsm[BATCH * C_MID * C_MID];
__device__ __align__(256) float d_phiT[C_IN * C_MID];
__device__ __align__(256) float d_q[C_IN];
__device__ __align__(256) float d_og[C_IN];
__device__ __align__(256) float d_ws[BATCH * C_MID];
__device__ __align__(256) float d_gs[BATCH * C_MID];
__device__ __align__(256) float d_Gq[BATCH * C_IN];
__device__ __align__(256) float d_up[BATCH * C_IN];
__device__ __align__(256) float d_cvec[BATCH * C_IN];
__device__ __align__(256) float d_Ttp[BATCH * NSP];
__device__ __align__(256) float d_Tg[BATCH * NSP];
__device__ __align__(256) float d_beta[BATCH];
__device__ float d_alpha;

__constant__ unsigned char c_TI[10] = {0,1,1,2,2,2,3,3,3,3};
__constant__ unsigned char c_TJ[10] = {0,0,1,0,1,2,0,1,2,3};

// ---------------------------------------------------------------------------
// Helpers
// ---------------------------------------------------------------------------
__device__ __forceinline__ void mma_tf32(float c[4],
                                         uint32_t a0, uint32_t a1, uint32_t a2, uint32_t a3,
                                         uint32_t b0, uint32_t b1) {
    asm volatile("mma.sync.aligned.m16n8k8.row.col.f32.tf32.tf32.f32 "
                 "{%0,%1,%2,%3}, {%4,%5,%6,%7}, {%8,%9}, {%0,%1,%2,%3};"
                 : "+f"(c[0]), "+f"(c[1]), "+f"(c[2]), "+f"(c[3])
                 : "r"(a0), "r"(a1), "r"(a2), "r"(a3), "r"(b0), "r"(b1));
}

__device__ __forceinline__ uint32_t fbits(float f) { return __float_as_uint(f); }

// round to nearest tf32 (applied at smem store / intermediate writes)
__device__ __forceinline__ float rtf(float f) {
    uint32_t u;
    asm("cvt.rna.tf32.f32 %0, %1;" : "=r"(u) : "f"(f));
    return __uint_as_float(u);
}
__device__ __forceinline__ float4 rtf4(float4 v) {
    return make_float4(rtf(v.x), rtf(v.y), rtf(v.z), rtf(v.w));
}

__device__ __forceinline__ float warp_red(float a) {
#pragma unroll
    for (int o = 16; o; o >>= 1) a += __shfl_xor_sync(0xffffffffu, a, o);
    return a;
}
__device__ __forceinline__ float warp_dot(const float* __restrict__ row,
                                          const float* __restrict__ v, int K) {
    int lane = threadIdx.x & 31;
    float a = 0.f;
    for (int k = lane; k < K; k += 32) a += row[k] * v[k];
    return warp_red(a);
}
__device__ __forceinline__ float warp_dot256(const float* __restrict__ row,
                                             const float* __restrict__ v) {
    int lane = threadIdx.x & 31;
    float4 r0 = *(const float4*)(row + lane * 4);
    float4 r1 = *(const float4*)(row + 128 + lane * 4);
    float4 v0 = *(const float4*)(v + lane * 4);
    float4 v1 = *(const float4*)(v + 128 + lane * 4);
    float a = r0.x * v0.x + r0.y * v0.y + r0.z * v0.z + r0.w * v0.w
            + r1.x * v1.x + r1.y * v1.y + r1.z * v1.z + r1.w * v1.w;
    return warp_red(a);
}
__device__ __forceinline__ float warp_dot128(const float* __restrict__ row,
                                             const float* __restrict__ v) {
    int lane = threadIdx.x & 31;
    float4 r0 = *(const float4*)(row + lane * 4);
    float4 v0 = *(const float4*)(v + lane * 4);
    float a = r0.x * v0.x + r0.y * v0.y + r0.z * v0.z + r0.w * v0.w;
    return warp_red(a);
}

// ---------------------------------------------------------------------------
// 64x128 tile TC GEMM accumulate (shared by t1 / final kernels)
// A row-major [*,lda], B row-major [K, ldb], acc[2][4][4]
// ---------------------------------------------------------------------------
__device__ __forceinline__ void tc_64x128(const float* __restrict__ A, int lda,
                                          const float* __restrict__ B, int ldb,
                                          int m0, int n0, int K,
                                          float* As, float* Bs,
                                          float acc[2][4][4]) {
    const int tid = threadIdx.x;
    const int lane = tid & 31, warp = tid >> 5;
    const int wm = warp >> 2, wn = warp & 3;
    const int gq = lane >> 2, tg = lane & 3;
    const int alr = tid >> 3, alc = (tid & 7) * 4;
    const int blr = tid >> 3, bf4 = (tid & 7);

    for (int k0 = 0; k0 < K; k0 += 32) {
        float4 va0 = *(const float4*)(A + (size_t)(m0 + alr) * lda + k0 + alc);
        float4 va1 = *(const float4*)(A + (size_t)(m0 + alr + 32) * lda + k0 + alc);
        float4 vb[4];
#pragma unroll
        for (int i = 0; i < 4; i++)
            vb[i] = *(const float4*)(B + (size_t)(k0 + blr) * ldb + n0 + (bf4 + 8 * i) * 4);
        __syncthreads();
        *(float4*)&As[alr * 36 + alc] = rtf4(va0);
        *(float4*)&As[(alr + 32) * 36 + alc] = rtf4(va1);
#pragma unroll
        for (int i = 0; i < 4; i++)
            *(float4*)&Bs[blr * 136 + (bf4 + 8 * i) * 4] = rtf4(vb[i]);
        __syncthreads();
#pragma unroll
        for (int kk = 0; kk < 32; kk += 8) {
            uint32_t a[2][4], b[4][2];
#pragma unroll
            for (int ma = 0; ma < 2; ma++) {
                int rb = wm * 32 + ma * 16 + gq;
                a[ma][0] = fbits(As[rb * 36 + kk + tg]);
                a[ma][1] = fbits(As[(rb + 8) * 36 + kk + tg]);
                a[ma][2] = fbits(As[rb * 36 + kk + 4 + tg]);
                a[ma][3] = fbits(As[(rb + 8) * 36 + kk + 4 + tg]);
            }
#pragma unroll
            for (int na = 0; na < 4; na++) {
                int cb = wn * 32 + na * 8 + gq;
                b[na][0] = fbits(Bs[(kk + tg) * 136 + cb]);
                b[na][1] = fbits(Bs[(kk + 4 + tg) * 136 + cb]);
            }
#pragma unroll
            for (int ma = 0; ma < 2; ma++)
#pragma unroll
                for (int na = 0; na < 4; na++)
                    mma_tf32(acc[ma][na], a[ma][0], a[ma][1], a[ma][2], a[ma][3],
                             b[na][0], b[na][1]);
        }
    }
}

// ---------------------------------------------------------------------------
// K1: T1 = theta_w @ X  (TC, blocks x<32), plus init blocks (x==32):
// zero d_G/d_s, compute q, og, alpha, phiT
// grid (33, 2, 4)
// ---------------------------------------------------------------------------
__global__ void __launch_bounds__(256) t1_kernel(const float* __restrict__ x,
                                                 const float* __restrict__ theta_w,
                                                 const float* __restrict__ phi_w,
                                                 const float* __restrict__ theta_b,
                                                 const float* __restrict__ g_b,
                                                 const float* __restrict__ out_w,
                                                 const float* __restrict__ phi_b) {
    const int tid = threadIdx.x;
    if (blockIdx.x < 32) {
        __shared__ float As[64 * 36];
        __shared__ float Bs[32 * 136];
        const int bz = blockIdx.z;
        const int m0 = blockIdx.y * 64;
        const int n0 = blockIdx.x * 128;
        float acc[2][4][4] = {};
        tc_64x128(theta_w, 256, x + (size_t)bz * C_IN * NSP, NSP, m0, n0, 256, As, Bs, acc);

        float* C = d_T1 + (size_t)bz * C_MID * NSP;
        const int lane = tid & 31, warp = tid >> 5;
        const int wm = warp >> 2, wn = warp & 3;
        const int gq = lane >> 2, tg = lane & 3;
#pragma unroll
        for (int ma = 0; ma < 2; ma++) {
            int rm = m0 + wm * 32 + ma * 16 + gq;
#pragma unroll
            for (int na = 0; na < 4; na++) {
                int cn = n0 + wn * 32 + na * 8 + 2 * tg;
                *(float2*)(C + (size_t)rm * NSP + cn) =
                    make_float2(rtf(acc[ma][na][0]), rtf(acc[ma][na][1]));
                *(float2*)(C + (size_t)(rm + 8) * NSP + cn) =
                    make_float2(rtf(acc[ma][na][2]), rtf(acc[ma][na][3]));
            }
        }
    } else {
        const int sid = blockIdx.y * 4 + blockIdx.z;   // 0..7
        // zero G slab (8192 float4 per slab)
        float4* G4 = (float4*)d_G;
#pragma unroll 4
        for (int i = 0; i < 32; i++)
            G4[sid * 8192 + i * 256 + tid] = make_float4(0, 0, 0, 0);
        if (sid == 1) {
            ((float4*)d_s)[tid] = make_float4(0, 0, 0, 0);
        } else if (sid == 2) {
            // q, og, alpha
            __shared__ float tb[C_MID], gb[C_MID];
            if (tid < C_MID) { tb[tid] = theta_b[tid]; gb[tid] = g_b[tid]; }
            __syncthreads();
            float a = 0.f;
#pragma unroll 8
            for (int k = 0; k < C_MID; k++) a += phi_w[k * C_IN + tid] * tb[k];
            d_q[tid] = a;
            const int warp = tid >> 5, lane = tid & 31;
            for (int i = 0; i < 32; i++) {
                int r = warp * 32 + i;
                float v = warp_dot128(out_w + r * C_MID, gb);
                if (lane == 0) d_og[r] = v;
            }
            if (warp == 0) {
                float al = phi_b[lane] * tb[lane] + phi_b[lane + 32] * tb[lane + 32]
                         + phi_b[lane + 64] * tb[lane + 64] + phi_b[lane + 96] * tb[lane + 96];
                al = warp_red(al);
                if (lane == 0) d_alpha = al;
            }
        } else if (sid == 3) {
            // phiT[c*128 + j] = phi_w[j*256 + c]
            for (int idx = tid; idx < C_IN * C_MID; idx += 256) {
                int j = idx >> 8, c = idx & 255;       // read-coalesced over phi_w
                d_phiT[c * C_MID + j] = phi_w[idx];
            }
        }
    }
}

// ---------------------------------------------------------------------------
// Gram via tf32 TC (rounded). triangle+mirror, split-K=4, + row sums.
// ---------------------------------------------------------------------------
__global__ void __launch_bounds__(256) gram_tc(const float* __restrict__ x) {
    const int t = blockIdx.x;
    const int ti = c_TI[t], tj = c_TJ[t];
    const int i0 = ti * 64, j0 = tj * 64;
    const int kbase = blockIdx.y * 1024;
    const int bz = blockIdx.z;
    const float* X = x + (size_t)bz * C_IN * NSP;

    __shared__ float As[64 * 36];
    __shared__ float Bs[64 * 36];

    const int tid = threadIdx.x;
    const int lane = tid & 31, warp = tid >> 5;
    const int wm = warp >> 2, wn = warp & 3;
    const int lr = tid >> 3;
    const int lc = (tid & 7) * 4;
    const int gq = lane >> 2, tg = lane & 3;

    float acc[2][2][4] = {};
    float s0 = 0.f, s1 = 0.f;
    const bool do_s = (tj == 0);

    for (int k0 = 0; k0 < 1024; k0 += 32) {
        float4 va0 = *(const float4*)(X + (size_t)(i0 + lr) * NSP + kbase + k0 + lc);
        float4 va1 = *(const float4*)(X + (size_t)(i0 + lr + 32) * NSP + kbase + k0 + lc);
        float4 vb0 = *(const float4*)(X + (size_t)(j0 + lr) * NSP + kbase + k0 + lc);
        float4 vb1 = *(const float4*)(X + (size_t)(j0 + lr + 32) * NSP + kbase + k0 + lc);
        if (do_s) {
            s0 += va0.x + va0.y + va0.z + va0.w;
            s1 += va1.x + va1.y + va1.z + va1.w;
        }
        __syncthreads();
        *(float4*)&As[lr * 36 + lc] = rtf4(va0);
        *(float4*)&As[(lr + 32) * 36 + lc] = rtf4(va1);
        *(float4*)&Bs[lr * 36 + lc] = rtf4(vb0);
        *(float4*)&Bs[(lr + 32) * 36 + lc] = rtf4(vb1);
        __syncthreads();
#pragma unroll
        for (int kk = 0; kk < 32; kk += 8) {
            uint32_t a[2][4], b[2][2];
#pragma unroll
            for (int ma = 0; ma < 2; ma++) {
                int rb = wm * 32 + ma * 16 + gq;
                a[ma][0] = fbits(As[rb * 36 + kk + tg]);
                a[ma][1] = fbits(As[(rb + 8) * 36 + kk + tg]);
                a[ma][2] = fbits(As[rb * 36 + kk + 4 + tg]);
                a[ma][3] = fbits(As[(rb + 8) * 36 + kk + 4 + tg]);
            }
#pragma unroll
            for (int na = 0; na < 2; na++) {
                int cb = wn * 16 + na * 8 + gq;
                b[na][0] = fbits(Bs[cb * 36 + kk + tg]);
                b[na][1] = fbits(Bs[cb * 36 + kk + 4 + tg]);
            }
#pragma unroll
            for (int ma = 0; ma < 2; ma++)
#pragma unroll
                for (int na = 0; na < 2; na++)
                    mma_tf32(acc[ma][na], a[ma][0], a[ma][1], a[ma][2], a[ma][3],
                             b[na][0], b[na][1]);
        }
    }

    float* Gp = d_G + (size_t)bz * CC;
#pragma unroll
    for (int ma = 0; ma < 2; ma++) {
        int rr = i0 + wm * 32 + ma * 16 + gq;
#pragma unroll
        for (int na = 0; na < 2; na++) {
            int cn = j0 + wn * 16 + na * 8 + 2 * tg;
            atomicAdd(&Gp[(size_t)rr * 256 + cn],           acc[ma][na][0]);
            atomicAdd(&Gp[(size_t)rr * 256 + cn + 1],       acc[ma][na][1]);
            atomicAdd(&Gp[(size_t)(rr + 8) * 256 + cn],     acc[ma][na][2]);
            atomicAdd(&Gp[(size_t)(rr + 8) * 256 + cn + 1], acc[ma][na][3]);
            if (ti != tj) {
                atomicAdd(&Gp[(size_t)cn * 256 + rr],           acc[ma][na][0]);
                atomicAdd(&Gp[(size_t)(cn + 1) * 256 + rr],     acc[ma][na][1]);
                atomicAdd(&Gp[(size_t)cn * 256 + rr + 8],       acc[ma][na][2]);
                atomicAdd(&Gp[(size_t)(cn + 1) * 256 + rr + 8], acc[ma][na][3]);
            }
        }
    }
    if (do_s) {
        atomicAdd(&d_s[bz * C_IN + i0 + lr], s0);
        atomicAdd(&d_s[bz * C_IN + i0 + lr + 32], s1);
    }
}

// ---------------------------------------------------------------------------
// 64x64 tile TC GEMM (rounded), C row-major ldc
// ---------------------------------------------------------------------------
__device__ __forceinline__ void tc64g(const float* __restrict__ A, int lda,
                                      const float* __restrict__ B, int ldb,
                                      float* __restrict__ C, int ldc,
                                      int K, int i0, int j0, float* sm) {
    float* As = sm;              // 64*36
    float* Bs = sm + 64 * 36;    // 32*68
    const int tid = threadIdx.x;
    const int lane = tid & 31, warp = tid >> 5;
    const int wm = warp >> 2, wn = warp & 3;
    const int gq = lane >> 2, tg = lane & 3;
    const int lr = tid >> 3, lc = (tid & 7) * 4;
    const int bk = tid >> 4, bn = (tid & 15) * 4;

    float acc[2][2][4] = {};

    for (int k0 = 0; k0 < K; k0 += 32) {
        float4 va0 = *(const float4*)(A + (size_t)(i0 + lr) * lda + k0 + lc);
        float4 va1 = *(const float4*)(A + (size_t)(i0 + lr + 32) * lda + k0 + lc);
        float4 vb0 = *(const float4*)(B + (size_t)(k0 + bk) * ldb + j0 + bn);
        float4 vb1 = *(const float4*)(B + (size_t)(k0 + bk + 16) * ldb + j0 + bn);
        __syncthreads();
        *(float4*)&As[lr * 36 + lc] = rtf4(va0);
        *(float4*)&As[(lr + 32) * 36 + lc] = rtf4(va1);
        *(float4*)&Bs[bk * 68 + bn] = rtf4(vb0);
        *(float4*)&Bs[(bk + 16) * 68 + bn] = rtf4(vb1);
        __syncthreads();
#pragma unroll
        for (int kk = 0; kk < 32; kk += 8) {
            uint32_t a[2][4], b[2][2];
#pragma unroll
            for (int ma = 0; ma < 2; ma++) {
                int rb = wm * 32 + ma * 16 + gq;
                a[ma][0] = fbits(As[rb * 36 + kk + tg]);
                a[ma][1] = fbits(As[(rb + 8) * 36 + kk + tg]);
                a[ma][2] = fbits(As[rb * 36 + kk + 4 + tg]);
                a[ma][3] = fbits(As[(rb + 8) * 36 + kk + 4 + tg]);
            }
#pragma unroll
            for (int na = 0; na < 2; na++) {
                int cb = wn * 16 + na * 8 + gq;
                b[na][0] = fbits(Bs[(kk + tg) * 68 + cb]);
                b[na][1] = fbits(Bs[(kk + 4 + tg) * 68 + cb]);
            }
#pragma unroll
            for (int ma = 0; ma < 2; ma++)
#pragma unroll
                for (int na = 0; na < 2; na++)
                    mma_tf32(acc[ma][na], a[ma][0], a[ma][1], a[ma][2], a[ma][3],
                             b[na][0], b[na][1]);
        }
    }

#pragma unroll
    for (int ma = 0; ma < 2; ma++) {
        int rm = i0 + wm * 32 + ma * 16 + gq;
#pragma unroll
        for (int na = 0; na < 2; na++) {
            int cn = j0 + wn * 16 + na * 8 + 2 * tg;
            *(float2*)(C + (size_t)rm * ldc + cn) =
                make_float2(rtf(acc[ma][na][0]), rtf(acc[ma][na][1]));
            *(float2*)(C + (size_t)(rm + 8) * ldc + cn) =
                make_float2(rtf(acc[ma][na][2]), rtf(acc[ma][na][3]));
        }
    }
}

// ---------------------------------------------------------------------------
// mid1: blocks 0..31 TC: B1_b = g_w @ G_b  [128x256 K=256]
//       blocks 32..63: sv1: ws, gs, Gq, beta
// ---------------------------------------------------------------------------
__global__ void __launch_bounds__(256) mid1(const float* __restrict__ g_w,
                                            const float* __restrict__ phi_w) {
    __shared__ float sm[64 * 36 + 32 * 68];
    const int b = blockIdx.x;
    const int tid = threadIdx.x, warp = tid >> 5, lane = tid & 31;

    if (b < 32) {
        int bz = b >> 3, t = b & 7;
        tc64g(g_w, 256, d_G + (size_t)bz * CC, 256,
              d_B1 + (size_t)bz * C_MID * C_IN, 256,
              256, (t >> 2) * 64, (t & 3) * 64, sm);
    } else {
        int b2 = b - 32;
        int bz = b2 >> 3, sub = b2 & 7;
        float* sv = sm;
        float* qv = sm + 256;
        sv[tid] = d_s[bz * C_IN + tid];
        qv[tid] = d_q[tid];
        __syncthreads();
        int wslot = sub * 8 + warp;       // 0..63
        if (wslot < 16) {
            int r0 = wslot * 8;
#pragma unroll
            for (int d = 0; d < 8; d++) {
                float v = warp_dot256(phi_w + (size_t)(r0 + d) * 256, sv);
                if (lane == 0) d_ws[bz * C_MID + r0 + d] = v;
            }
            if (wslot == 0) {
                float bt = warp_dot256(sv, qv);
                if (lane == 0) d_beta[bz] = bt;
            }
        } else if (wslot < 32) {
            int r0 = (wslot - 16) * 8;
#pragma unroll
            for (int d = 0; d < 8; d++) {
                float v = warp_dot256(g_w + (size_t)(r0 + d) * 256, sv);
                if (lane == 0) d_gs[bz * C_MID + r0 + d] = v;
            }
        } else {
            int r0 = (wslot - 32) * 8;
#pragma unroll
            for (int d = 0; d < 8; d++) {
                float v = warp_dot256(d_G + (size_t)bz * CC + (size_t)(r0 + d) * 256, qv);
                if (lane == 0) d_Gq[bz * C_IN + r0 + d] = v;
            }
        }
    }
}

// ---------------------------------------------------------------------------
// mid2: blocks 0..15 TC: B_small_b = B1_b @ phiT  [128x128 K=256]
//       blocks 16..47: sv2: gq2 (redundant per block), up, cvec
// ---------------------------------------------------------------------------
__global__ void __launch_bounds__(256) mid2(const float* __restrict__ g_w,
                                            const float* __restrict__ out_w,
                                            const float* __restrict__ out_b) {
    __shared__ float sm[64 * 36 + 32 * 68];
    const int b = blockIdx.x;
    const int tid = threadIdx.x, warp = tid >> 5, lane = tid & 31;

    if (b < 16) {
        int bz = b >> 2, t = b & 3;
        tc64g(d_B1 + (size_t)bz * C_MID * C_IN, 256, d_phiT, 128,
              d_Bsm + (size_t)bz * C_MID * C_MID, 128,
              256, (t >> 1) * 64, (t & 1) * 64, sm);
    } else {
        int b2 = b - 16;
        int bz = b2 >> 3, sub = b2 & 7;
        float* Gqs = sm;            // 256
        float* gss = sm + 256;      // 128
        float* gq2 = sm + 384;      // 128
        Gqs[tid] = d_Gq[bz * C_IN + tid];
        if (tid < C_MID) gss[tid] = d_gs[bz * C_MID + tid];
        __syncthreads();
#pragma unroll
        for (int d = 0; d < 16; d++) {
            int r = warp * 16 + d;
            float v = warp_dot256(g_w + (size_t)r * 256, Gqs);
            if (lane == 0) gq2[r] = v;
        }
        __syncthreads();
        const float alpha = d_alpha;
        const float bcoef = d_beta[bz] * INVN + alpha;
#pragma unroll
        for (int i = 0; i < 4; i++) {
            int r = sub * 32 + warp * 4 + i;
            float u = warp_dot128(out_w + (size_t)r * C_MID, gss) * INVN;
            float cv = warp_dot128(out_w + (size_t)r * C_MID, gq2) * INVN +
                       alpha * u + bcoef * d_og[r] + out_b[r];
            if (lane == 0) {
                d_up[bz * C_IN + r] = u;
                d_cvec[bz * C_IN + r] = cv;
            }
        }
    }
}

// ---------------------------------------------------------------------------
// T2 = B_small @ T1  [128x4096 K=128], tile 128x64, grid (64, BATCH)
// Epilogue also computes Ttp = phi_b . T1col, Tg = (ws . T1col)/N + Ttp
// ---------------------------------------------------------------------------
__global__ void __launch_bounds__(256) t2_kernel(const float* __restrict__ phi_b) {
    const int bz = blockIdx.y;
    const int n0 = blockIdx.x * 64;
    const float* A = d_Bsm + (size_t)bz * C_MID * C_MID;
    const float* B = d_T1 + (size_t)bz * C_MID * NSP;
    float* C = d_T2 + (size_t)bz * C_MID * NSP;

    __shared__ float As[128 * 36];
    __shared__ float Bs[32 * 68];
    __shared__ float pbs[C_MID], wss[C_MID];
    __shared__ float redtp[4 * 64], redws[4 * 64];

    const int tid = threadIdx.x;
    const int lane = tid & 31, warp = tid >> 5;
    const int wm = warp >> 1, wn = warp & 1;
    const int gq = lane >> 2, tg = lane & 3;
    const int ar = tid >> 1, ac = (tid & 1) * 16;
    const int bk = tid >> 3, bn = (tid & 7) * 4;
    const int rc = tid & 63, rk = tid >> 6;

    if (tid < C_MID) {
        pbs[tid] = phi_b[tid];
        wss[tid] = d_ws[bz * C_MID + tid];
    }

    float acc[2][4][4] = {};
    float tpa = 0.f, wsa = 0.f;

    for (int k0 = 0; k0 < 128; k0 += 32) {
        float4 va[4];
#pragma unroll
        for (int j = 0; j < 4; j++)
            va[j] = *(const float4*)(A + (size_t)ar * C_MID + k0 + ac + 4 * j);
        float4 vb0 = *(const float4*)(B + (size_t)(k0 + bk) * NSP + n0 + bn);
        float4 vb1 = *(const float4*)(B + (size_t)(k0 + bk) * NSP + n0 + bn + 32);
        __syncthreads();
#pragma unroll
        for (int j = 0; j < 4; j++)
            *(float4*)&As[ar * 36 + ac + 4 * j] = va[j];   // already rounded
        *(float4*)&Bs[bk * 68 + bn] = vb0;
        *(float4*)&Bs[bk * 68 + bn + 32] = vb1;
        __syncthreads();
#pragma unroll
        for (int kk = 0; kk < 32; kk += 8) {
            uint32_t a[2][4], b[4][2];
#pragma unroll
            for (int ma = 0; ma < 2; ma++) {
                int rb = wm * 32 + ma * 16 + gq;
                a[ma][0] = fbits(As[rb * 36 + kk + tg]);
                a[ma][1] = fbits(As[(rb + 8) * 36 + kk + tg]);
                a[ma][2] = fbits(As[rb * 36 + kk + 4 + tg]);
                a[ma][3] = fbits(As[(rb + 8) * 36 + kk + 4 + tg]);
            }
#pragma unroll
            for (int na = 0; na < 4; na++) {
                int cb = wn * 32 + na * 8 + gq;
                b[na][0] = fbits(Bs[(kk + tg) * 68 + cb]);
                b[na][1] = fbits(Bs[(kk + 4 + tg) * 68 + cb]);
            }
#pragma unroll
            for (int ma = 0; ma < 2; ma++)
#pragma unroll
                for (int na = 0; na < 4; na++)
                    mma_tf32(acc[ma][na], a[ma][0], a[ma][1], a[ma][2], a[ma][3],
                             b[na][0], b[na][1]);
        }
        // column partial sums for Ttp / Tws
#pragma unroll
        for (int k = 0; k < 8; k++) {
            int kk2 = rk * 8 + k;
            float bv = Bs[kk2 * 68 + rc];
            tpa += pbs[k0 + kk2] * bv;
            wsa += wss[k0 + kk2] * bv;
        }
    }

#pragma unroll
    for (int ma = 0; ma < 2; ma++) {
        int rm = wm * 32 + ma * 16 + gq;
#pragma unroll
        for (int na = 0; na < 4; na++) {
            int cn = n0 + wn * 32 + na * 8 + 2 * tg;
            *(float2*)(C + (size_t)rm * NSP + cn) =
                make_float2(rtf(acc[ma][na][0]), rtf(acc[ma][na][1]));
            *(float2*)(C + (size_t)(rm + 8) * NSP + cn) =
                make_float2(rtf(acc[ma][na][2]), rtf(acc[ma][na][3]));
        }
    }

    redtp[rk * 64 + rc] = tpa;
    redws[rk * 64 + rc] = wsa;
    __syncthreads();
    if (tid < 64) {
        float t = redtp[tid] + redtp[64 + tid] + redtp[128 + tid] + redtp[192 + tid];
        float w = redws[tid] + redws[64 + tid] + redws[128 + tid] + redws[192 + tid];
        d_Ttp[bz * NSP + n0 + tid] = t;
        d_Tg[bz * NSP + n0 + tid] = w * INVN + t;
    }
}

// ---------------------------------------------------------------------------
// final: out = out_w @ T2 * INVN + up*Ttp + og*Tg + cvec + x
// tile 64x128, grid (32, 4, BATCH)
// ---------------------------------------------------------------------------
__global__ void __launch_bounds__(256) final_k(const float* __restrict__ x,
                                               const float* __restrict__ out_w,
                                               float* __restrict__ out) {
    __shared__ float As[64 * 36];
    __shared__ float Bs[32 * 136];
    const int bz = blockIdx.z;
    const int m0 = blockIdx.y * 64;
    const int n0 = blockIdx.x * 128;
    const float* Xb = x + (size_t)bz * C_IN * NSP;
    float* Ob = out + (size_t)bz * C_IN * NSP;

    float acc[2][4][4] = {};
    tc_64x128(out_w, C_MID, d_T2 + (size_t)bz * C_MID * NSP, NSP, m0, n0, 128, As, Bs, acc);

    const int tid = threadIdx.x;
    const int lane = tid & 31, warp = tid >> 5;
    const int wm = warp >> 2, wn = warp & 3;
    const int gq = lane >> 2, tg = lane & 3;

    const float* cb = d_cvec + bz * C_IN;
    const float* ub = d_up + bz * C_IN;
    const float* tpb = d_Ttp + (size_t)bz * NSP;
    const float* tgb = d_Tg + (size_t)bz * NSP;
#pragma unroll
    for (int ma = 0; ma < 2; ma++) {
        int rm = m0 + wm * 32 + ma * 16 + gq;
        float c0 = cb[rm], c1 = cb[rm + 8];
        float u0 = ub[rm], u1 = ub[rm + 8];
        float o0 = d_og[rm], o1 = d_og[rm + 8];
#pragma unroll
        for (int na = 0; na < 4; na++) {
            int cn = n0 + wn * 32 + na * 8 + 2 * tg;
            float2 tp = *(const float2*)(tpb + cn);
            float2 tg2 = *(const float2*)(tgb + cn);
            float2 x0 = *(const float2*)(Xb + (size_t)rm * NSP + cn);
            float2 x1 = *(const float2*)(Xb + (size_t)(rm + 8) * NSP + cn);
            *(float2*)(Ob + (size_t)rm * NSP + cn) = make_float2(
                acc[ma][na][0] * INVN + u0 * tp.x + o0 * tg2.x + c0 + x0.x,
                acc[ma][na][1] * INVN + u0 * tp.y + o0 * tg2.y + c0 + x0.y);
            *(float2*)(Ob + (size_t)(rm + 8) * NSP + cn) = make_float2(
                acc[ma][na][2] * INVN + u1 * tp.x + o1 * tg2.x + c1 + x1.x,
                acc[ma][na][3] * INVN + u1 * tp.y + o1 * tg2.y + c1 + x1.y);
        }
    }
}

// ---------------------------------------------------------------------------
// Host launcher — 6 kernels
// ---------------------------------------------------------------------------
extern "C" void kernel_launch(void* const* d_in, const int* in_sizes, int n_in,
                              void* d_out, int out_size) {
    const float* x       = (const float*)d_in[0];
    const float* g_w     = (const float*)d_in[1];
    const float* g_b     = (const float*)d_in[2];
    const float* theta_w = (const float*)d_in[3];
    const float* theta_b = (const float*)d_in[4];
    const float* phi_w   = (const float*)d_in[5];
    const float* phi_b   = (const float*)d_in[6];
    const float* out_w   = (const float*)d_in[7];
    const float* out_b   = (const float*)d_in[8];
    float* out = (float*)d_out;

    t1_kernel<<<dim3(33, 2, 4), 256>>>(x, theta_w, phi_w, theta_b, g_b, out_w, phi_b);
    gram_tc<<<dim3(10, 4, BATCH), 256>>>(x);
    mid1<<<64, 256>>>(g_w, phi_w);
    mid2<<<48, 256>>>(g_w, out_w, out_b);
    t2_kernel<<<dim3(64, BATCH), 256>>>(phi_b);
    final_k<<<dim3(32, 4, BATCH), 256>>>(x, out_w, out);
}

// round 6
// speedup vs baseline: 4.1935x; 1.4273x over previous
#include <cuda_runtime.h>
#include <cstdint>

#define BATCH 4
#define C_IN 256
#define C_MID 128
#define NSP 4096
#define INVN (1.0f/4096.0f)

// ---------------------------------------------------------------------------
// Device scratch
// ---------------------------------------------------------------------------
__device__ __align__(256) float d_Tph[BATCH * C_MID * NSP];  // phi_w @ X
__device__ __align__(256) float d_Tg[BATCH * C_MID * NSP];   // g_w @ X
__device__ __align__(256) float d_M[BATCH * C_MID * C_MID];  // Tg @ Tph^T (raw)
__device__ __align__(256) float d_gs[BATCH * C_MID];         // row sums of Tg
__device__ __align__(256) float d_ws[BATCH * C_MID];         // row sums of Tph
__device__ __align__(256) float d_Af[BATCH * C_IN * C_IN];   // folded operator
__device__ __align__(256) float d_cvec[BATCH * C_IN];        // per-batch bias

// ---------------------------------------------------------------------------
// Helpers
// ---------------------------------------------------------------------------
__device__ __forceinline__ void mma_tf32(float c[4],
                                         uint32_t a0, uint32_t a1, uint32_t a2, uint32_t a3,
                                         uint32_t b0, uint32_t b1) {
    asm volatile("mma.sync.aligned.m16n8k8.row.col.f32.tf32.tf32.f32 "
                 "{%0,%1,%2,%3}, {%4,%5,%6,%7}, {%8,%9}, {%0,%1,%2,%3};"
                 : "+f"(c[0]), "+f"(c[1]), "+f"(c[2]), "+f"(c[3])
                 : "r"(a0), "r"(a1), "r"(a2), "r"(a3), "r"(b0), "r"(b1));
}

__device__ __forceinline__ uint32_t fbits(float f) { return __float_as_uint(f); }

__device__ __forceinline__ float rtf(float f) {
    uint32_t u;
    asm("cvt.rna.tf32.f32 %0, %1;" : "=r"(u) : "f"(f));
    return __uint_as_float(u);
}
__device__ __forceinline__ float4 rtf4(float4 v) {
    return make_float4(rtf(v.x), rtf(v.y), rtf(v.z), rtf(v.w));
}

__device__ __forceinline__ float warp_dot128(const float* __restrict__ row,
                                             const float* __restrict__ v) {
    int lane = threadIdx.x & 31;
    float4 r0 = *(const float4*)(row + lane * 4);
    float4 v0 = *(const float4*)(v + lane * 4);
    float a = r0.x * v0.x + r0.y * v0.y + r0.z * v0.z + r0.w * v0.w;
#pragma unroll
    for (int o = 16; o; o >>= 1) a += __shfl_xor_sync(0xffffffffu, a, o);
    return a;
}

// ---------------------------------------------------------------------------
// 64x128-tile tf32 GEMM accumulate: A row-major [.,lda], B row-major [K,ldb]
// ---------------------------------------------------------------------------
__device__ __forceinline__ void tc_64x128(const float* __restrict__ A, int lda,
                                          const float* __restrict__ B, int ldb,
                                          int m0, int n0, int K,
                                          float* As, float* Bs,
                                          float acc[2][4][4]) {
    const int tid = threadIdx.x;
    const int lane = tid & 31, warp = tid >> 5;
    const int wm = warp >> 2, wn = warp & 3;
    const int gq = lane >> 2, tg = lane & 3;
    const int alr = tid >> 3, alc = (tid & 7) * 4;
    const int blr = tid >> 3, bf4 = (tid & 7);

    for (int k0 = 0; k0 < K; k0 += 32) {
        float4 va0 = *(const float4*)(A + (size_t)(m0 + alr) * lda + k0 + alc);
        float4 va1 = *(const float4*)(A + (size_t)(m0 + alr + 32) * lda + k0 + alc);
        float4 vb[4];
#pragma unroll
        for (int i = 0; i < 4; i++)
            vb[i] = *(const float4*)(B + (size_t)(k0 + blr) * ldb + n0 + (bf4 + 8 * i) * 4);
        __syncthreads();
        *(float4*)&As[alr * 36 + alc] = rtf4(va0);
        *(float4*)&As[(alr + 32) * 36 + alc] = rtf4(va1);
#pragma unroll
        for (int i = 0; i < 4; i++)
            *(float4*)&Bs[blr * 136 + (bf4 + 8 * i) * 4] = rtf4(vb[i]);
        __syncthreads();
#pragma unroll
        for (int kk = 0; kk < 32; kk += 8) {
            uint32_t a[2][4], b[4][2];
#pragma unroll
            for (int ma = 0; ma < 2; ma++) {
                int rb = wm * 32 + ma * 16 + gq;
                a[ma][0] = fbits(As[rb * 36 + kk + tg]);
                a[ma][1] = fbits(As[(rb + 8) * 36 + kk + tg]);
                a[ma][2] = fbits(As[rb * 36 + kk + 4 + tg]);
                a[ma][3] = fbits(As[(rb + 8) * 36 + kk + 4 + tg]);
            }
#pragma unroll
            for (int na = 0; na < 4; na++) {
                int cb = wn * 32 + na * 8 + gq;
                b[na][0] = fbits(Bs[(kk + tg) * 136 + cb]);
                b[na][1] = fbits(Bs[(kk + 4 + tg) * 136 + cb]);
            }
#pragma unroll
            for (int ma = 0; ma < 2; ma++)
#pragma unroll
                for (int na = 0; na < 4; na++)
                    mma_tf32(acc[ma][na], a[ma][0], a[ma][1], a[ma][2], a[ma][3],
                             b[na][0], b[na][1]);
        }
    }
}

// ---------------------------------------------------------------------------
// proj: Tph = phi_w @ X, Tg = g_w @ X (shared X staging), + init side blocks
// grid (33, 2, 4): x<32 GEMM tiles, x==32 init
// ---------------------------------------------------------------------------
__global__ void __launch_bounds__(256) proj(const float* __restrict__ x,
                                            const float* __restrict__ phi_w,
                                            const float* __restrict__ g_w) {
    const int tid = threadIdx.x;
    if (blockIdx.x == 32) {
        const int sid = blockIdx.y * 4 + blockIdx.z;   // 0..7
        float4 z4 = make_float4(0, 0, 0, 0);
        float4* M4 = (float4*)d_M;
#pragma unroll
        for (int i = 0; i < 8; i++) M4[sid * 2048 + i * 256 + tid] = z4;
        if (sid == 0 && tid < 128) {
            ((float4*)d_gs)[tid] = z4;
            ((float4*)d_ws)[tid] = z4;
        }
        return;
    }

    __shared__ float As1[64 * 36], As2[64 * 36], Bs[32 * 136];
    const int bz = blockIdx.z;
    const int m0 = blockIdx.y * 64;
    const int n0 = blockIdx.x * 128;
    const float* X = x + (size_t)bz * C_IN * NSP;

    const int lane = tid & 31, warp = tid >> 5;
    const int wm = warp >> 2, wn = warp & 3;
    const int gq = lane >> 2, tg = lane & 3;
    const int alr = tid >> 3, alc = (tid & 7) * 4;
    const int blr = tid >> 3, bf4 = (tid & 7);

    float acc1[2][4][4] = {}, acc2[2][4][4] = {};

    for (int k0 = 0; k0 < 256; k0 += 32) {
        float4 p0 = *(const float4*)(phi_w + (size_t)(m0 + alr) * 256 + k0 + alc);
        float4 p1 = *(const float4*)(phi_w + (size_t)(m0 + alr + 32) * 256 + k0 + alc);
        float4 g0 = *(const float4*)(g_w + (size_t)(m0 + alr) * 256 + k0 + alc);
        float4 g1 = *(const float4*)(g_w + (size_t)(m0 + alr + 32) * 256 + k0 + alc);
        float4 vb[4];
#pragma unroll
        for (int i = 0; i < 4; i++)
            vb[i] = *(const float4*)(X + (size_t)(k0 + blr) * NSP + n0 + (bf4 + 8 * i) * 4);
        __syncthreads();
        *(float4*)&As1[alr * 36 + alc] = rtf4(p0);
        *(float4*)&As1[(alr + 32) * 36 + alc] = rtf4(p1);
        *(float4*)&As2[alr * 36 + alc] = rtf4(g0);
        *(float4*)&As2[(alr + 32) * 36 + alc] = rtf4(g1);
#pragma unroll
        for (int i = 0; i < 4; i++)
            *(float4*)&Bs[blr * 136 + (bf4 + 8 * i) * 4] = rtf4(vb[i]);
        __syncthreads();
#pragma unroll
        for (int kk = 0; kk < 32; kk += 8) {
            uint32_t a1[2][4], a2[2][4], b[4][2];
#pragma unroll
            for (int ma = 0; ma < 2; ma++) {
                int rb = wm * 32 + ma * 16 + gq;
                a1[ma][0] = fbits(As1[rb * 36 + kk + tg]);
                a1[ma][1] = fbits(As1[(rb + 8) * 36 + kk + tg]);
                a1[ma][2] = fbits(As1[rb * 36 + kk + 4 + tg]);
                a1[ma][3] = fbits(As1[(rb + 8) * 36 + kk + 4 + tg]);
                a2[ma][0] = fbits(As2[rb * 36 + kk + tg]);
                a2[ma][1] = fbits(As2[(rb + 8) * 36 + kk + tg]);
                a2[ma][2] = fbits(As2[rb * 36 + kk + 4 + tg]);
                a2[ma][3] = fbits(As2[(rb + 8) * 36 + kk + 4 + tg]);
            }
#pragma unroll
            for (int na = 0; na < 4; na++) {
                int cb = wn * 32 + na * 8 + gq;
                b[na][0] = fbits(Bs[(kk + tg) * 136 + cb]);
                b[na][1] = fbits(Bs[(kk + 4 + tg) * 136 + cb]);
            }
#pragma unroll
            for (int ma = 0; ma < 2; ma++)
#pragma unroll
                for (int na = 0; na < 4; na++) {
                    mma_tf32(acc1[ma][na], a1[ma][0], a1[ma][1], a1[ma][2], a1[ma][3],
                             b[na][0], b[na][1]);
                    mma_tf32(acc2[ma][na], a2[ma][0], a2[ma][1], a2[ma][2], a2[ma][3],
                             b[na][0], b[na][1]);
                }
        }
    }

    float* C1 = d_Tph + (size_t)bz * C_MID * NSP;
    float* C2 = d_Tg + (size_t)bz * C_MID * NSP;
#pragma unroll
    for (int ma = 0; ma < 2; ma++) {
        int rm = m0 + wm * 32 + ma * 16 + gq;
#pragma unroll
        for (int na = 0; na < 4; na++) {
            int cn = n0 + wn * 32 + na * 8 + 2 * tg;
            *(float2*)(C1 + (size_t)rm * NSP + cn) =
                make_float2(rtf(acc1[ma][na][0]), rtf(acc1[ma][na][1]));
            *(float2*)(C1 + (size_t)(rm + 8) * NSP + cn) =
                make_float2(rtf(acc1[ma][na][2]), rtf(acc1[ma][na][3]));
            *(float2*)(C2 + (size_t)rm * NSP + cn) =
                make_float2(rtf(acc2[ma][na][0]), rtf(acc2[ma][na][1]));
            *(float2*)(C2 + (size_t)(rm + 8) * NSP + cn) =
                make_float2(rtf(acc2[ma][na][2]), rtf(acc2[ma][na][3]));
        }
    }
}

// ---------------------------------------------------------------------------
// bsm: Mraw = Tg @ Tph^T (NT GEMM, split-K=8, atomics) + row sums gs/ws
// grid (4 tiles of 64x64, 8 k-chunks of 512, 4 batch)
// ---------------------------------------------------------------------------
__global__ void __launch_bounds__(256) bsm() {
    const int ti = blockIdx.x >> 1, tj = blockIdx.x & 1;
    const int i0 = ti * 64, j0 = tj * 64;
    const int kb = blockIdx.y * 512;
    const int bz = blockIdx.z;
    const float* A = d_Tg + (size_t)bz * C_MID * NSP;
    const float* B = d_Tph + (size_t)bz * C_MID * NSP;

    __shared__ float As[64 * 36];
    __shared__ float Bs[64 * 36];

    const int tid = threadIdx.x;
    const int lane = tid & 31, warp = tid >> 5;
    const int wm = warp >> 2, wn = warp & 3;
    const int lr = tid >> 3, lc = (tid & 7) * 4;
    const int gq = lane >> 2, tg = lane & 3;

    float acc[2][2][4] = {};
    float sa0 = 0.f, sa1 = 0.f, sb0 = 0.f, sb1 = 0.f;
    const bool dosum = (ti == tj);

    for (int k0 = 0; k0 < 512; k0 += 32) {
        float4 va0 = *(const float4*)(A + (size_t)(i0 + lr) * NSP + kb + k0 + lc);
        float4 va1 = *(const float4*)(A + (size_t)(i0 + lr + 32) * NSP + kb + k0 + lc);
        float4 vb0 = *(const float4*)(B + (size_t)(j0 + lr) * NSP + kb + k0 + lc);
        float4 vb1 = *(const float4*)(B + (size_t)(j0 + lr + 32) * NSP + kb + k0 + lc);
        if (dosum) {
            sa0 += va0.x + va0.y + va0.z + va0.w;
            sa1 += va1.x + va1.y + va1.z + va1.w;
            sb0 += vb0.x + vb0.y + vb0.z + vb0.w;
            sb1 += vb1.x + vb1.y + vb1.z + vb1.w;
        }
        __syncthreads();
        *(float4*)&As[lr * 36 + lc] = va0;       // already tf32-rounded values
        *(float4*)&As[(lr + 32) * 36 + lc] = va1;
        *(float4*)&Bs[lr * 36 + lc] = vb0;
        *(float4*)&Bs[(lr + 32) * 36 + lc] = vb1;
        __syncthreads();
#pragma unroll
        for (int kk = 0; kk < 32; kk += 8) {
            uint32_t a[2][4], b[2][2];
#pragma unroll
            for (int ma = 0; ma < 2; ma++) {
                int rb = wm * 32 + ma * 16 + gq;
                a[ma][0] = fbits(As[rb * 36 + kk + tg]);
                a[ma][1] = fbits(As[(rb + 8) * 36 + kk + tg]);
                a[ma][2] = fbits(As[rb * 36 + kk + 4 + tg]);
                a[ma][3] = fbits(As[(rb + 8) * 36 + kk + 4 + tg]);
            }
#pragma unroll
            for (int na = 0; na < 2; na++) {
                int cb = wn * 16 + na * 8 + gq;
                b[na][0] = fbits(Bs[cb * 36 + kk + tg]);
                b[na][1] = fbits(Bs[cb * 36 + kk + 4 + tg]);
            }
#pragma unroll
            for (int ma = 0; ma < 2; ma++)
#pragma unroll
                for (int na = 0; na < 2; na++)
                    mma_tf32(acc[ma][na], a[ma][0], a[ma][1], a[ma][2], a[ma][3],
                             b[na][0], b[na][1]);
        }
    }

    float* Mp = d_M + (size_t)bz * C_MID * C_MID;
#pragma unroll
    for (int ma = 0; ma < 2; ma++) {
        int rr = i0 + wm * 32 + ma * 16 + gq;
#pragma unroll
        for (int na = 0; na < 2; na++) {
            int cn = j0 + wn * 16 + na * 8 + 2 * tg;
            atomicAdd(&Mp[(size_t)rr * C_MID + cn],           acc[ma][na][0]);
            atomicAdd(&Mp[(size_t)rr * C_MID + cn + 1],       acc[ma][na][1]);
            atomicAdd(&Mp[(size_t)(rr + 8) * C_MID + cn],     acc[ma][na][2]);
            atomicAdd(&Mp[(size_t)(rr + 8) * C_MID + cn + 1], acc[ma][na][3]);
        }
    }
    if (dosum) {
#pragma unroll
        for (int o = 1; o < 8; o <<= 1) {
            sa0 += __shfl_xor_sync(0xffffffffu, sa0, o);
            sa1 += __shfl_xor_sync(0xffffffffu, sa1, o);
            sb0 += __shfl_xor_sync(0xffffffffu, sb0, o);
            sb1 += __shfl_xor_sync(0xffffffffu, sb1, o);
        }
        if ((tid & 7) == 0) {
            atomicAdd(&d_gs[bz * C_MID + i0 + lr], sa0);
            atomicAdd(&d_gs[bz * C_MID + i0 + lr + 32], sa1);
            atomicAdd(&d_ws[bz * C_MID + j0 + lr], sb0);
            atomicAdd(&d_ws[bz * C_MID + j0 + lr + 32], sb1);
        }
    }
}

// ---------------------------------------------------------------------------
// afold: per CTA: Wm = out_w[i0:+64,:] @ Mfull (rank-1 fused) in smem,
// then Afold[i0:+64, n0:+128] = Wm @ theta_w * INVN; cvec for n0==0 CTAs.
// grid (2 j-halves, 4 i-tiles, 4 batch)
// ---------------------------------------------------------------------------
__global__ void __launch_bounds__(256) afold(const float* __restrict__ out_w,
                                             const float* __restrict__ theta_w,
                                             const float* __restrict__ theta_b,
                                             const float* __restrict__ phi_b,
                                             const float* __restrict__ g_b,
                                             const float* __restrict__ out_b) {
    __shared__ float sm[11008];
    // layout: phase1: As [0,2304), Bs [2304,6656)
    //         Wm [0,8448) (64x132), Bs2 [8448,10560) (16x132)
    //         pbs 10560, wss 10688, tbs 10816  (128 each)
    float* pbs = sm + 10560;
    float* wss = sm + 10688;
    float* tbs = sm + 10816;

    const int bz = blockIdx.z;
    const int i0 = blockIdx.y * 64;
    const int n0 = blockIdx.x * 128;
    const float* Mraw = d_M + (size_t)bz * C_MID * C_MID;

    const int tid = threadIdx.x;
    const int lane = tid & 31, warp = tid >> 5;
    const int wm = warp >> 2, wn = warp & 3;
    const int gq = lane >> 2, tg = lane & 3;
    const int alr = tid >> 3, alc = (tid & 7) * 4;
    const int blr = tid >> 3, bf4 = (tid & 7);

    if (tid < 128) {
        pbs[tid] = phi_b[tid];
        wss[tid] = d_ws[bz * C_MID + tid];
        tbs[tid] = theta_b[tid];
    }
    __syncthreads();

    // ---- phase 1: Wm = out_w_slice @ Mfull (K=128) ----
    float* As = sm;
    float* Bs = sm + 2304;
    float accW[2][4][4] = {};

    for (int k0 = 0; k0 < 128; k0 += 32) {
        float4 va0 = *(const float4*)(out_w + (size_t)(i0 + alr) * C_MID + k0 + alc);
        float4 va1 = *(const float4*)(out_w + (size_t)(i0 + alr + 32) * C_MID + k0 + alc);
        const int krow = k0 + blr;
        const float gsv = d_gs[bz * C_MID + krow];
        const float gbv = g_b[krow];
        float4 vb[4];
#pragma unroll
        for (int i = 0; i < 4; i++) {
            int c = (bf4 + 8 * i) * 4;
            float4 mr = *(const float4*)(Mraw + (size_t)krow * C_MID + c);
            float4 pb = *(const float4*)&pbs[c];
            float4 wv = *(const float4*)&wss[c];
            vb[i].x = mr.x + gsv * pb.x + gbv * (wv.x + 4096.f * pb.x);
            vb[i].y = mr.y + gsv * pb.y + gbv * (wv.y + 4096.f * pb.y);
            vb[i].z = mr.z + gsv * pb.z + gbv * (wv.z + 4096.f * pb.z);
            vb[i].w = mr.w + gsv * pb.w + gbv * (wv.w + 4096.f * pb.w);
        }
        __syncthreads();
        *(float4*)&As[alr * 36 + alc] = rtf4(va0);
        *(float4*)&As[(alr + 32) * 36 + alc] = rtf4(va1);
#pragma unroll
        for (int i = 0; i < 4; i++)
            *(float4*)&Bs[blr * 136 + (bf4 + 8 * i) * 4] = rtf4(vb[i]);
        __syncthreads();
#pragma unroll
        for (int kk = 0; kk < 32; kk += 8) {
            uint32_t a[2][4], b[4][2];
#pragma unroll
            for (int ma = 0; ma < 2; ma++) {
                int rb = wm * 32 + ma * 16 + gq;
                a[ma][0] = fbits(As[rb * 36 + kk + tg]);
                a[ma][1] = fbits(As[(rb + 8) * 36 + kk + tg]);
                a[ma][2] = fbits(As[rb * 36 + kk + 4 + tg]);
                a[ma][3] = fbits(As[(rb + 8) * 36 + kk + 4 + tg]);
            }
#pragma unroll
            for (int na = 0; na < 4; na++) {
                int cb = wn * 32 + na * 8 + gq;
                b[na][0] = fbits(Bs[(kk + tg) * 136 + cb]);
                b[na][1] = fbits(Bs[(kk + 4 + tg) * 136 + cb]);
            }
#pragma unroll
            for (int ma = 0; ma < 2; ma++)
#pragma unroll
                for (int na = 0; na < 4; na++)
                    mma_tf32(accW[ma][na], a[ma][0], a[ma][1], a[ma][2], a[ma][3],
                             b[na][0], b[na][1]);
        }
    }

    // store Wm into smem [0,8448) (64 x 132), rounded
    __syncthreads();
    float* Wm = sm;
#pragma unroll
    for (int ma = 0; ma < 2; ma++) {
        int rm = wm * 32 + ma * 16 + gq;
#pragma unroll
        for (int na = 0; na < 4; na++) {
            int cn = wn * 32 + na * 8 + 2 * tg;
            Wm[rm * 132 + cn]           = rtf(accW[ma][na][0]);
            Wm[rm * 132 + cn + 1]       = rtf(accW[ma][na][1]);
            Wm[(rm + 8) * 132 + cn]     = rtf(accW[ma][na][2]);
            Wm[(rm + 8) * 132 + cn + 1] = rtf(accW[ma][na][3]);
        }
    }

    // ---- phase 2: Afold = Wm @ theta_w[:, n0:+128] * INVN ----
    float* Bs2 = sm + 8448;
    float accF[2][4][4] = {};
    const int trow = tid >> 4;           // 0..15
    const int tcol = (tid & 15) * 4;     // 0..60

    for (int k0 = 0; k0 < 128; k0 += 16) {
        float4 t0 = *(const float4*)(theta_w + (size_t)(k0 + trow) * C_IN + n0 + tcol);
        float4 t1 = *(const float4*)(theta_w + (size_t)(k0 + trow) * C_IN + n0 + tcol + 64);
        __syncthreads();
        *(float4*)&Bs2[trow * 132 + tcol] = rtf4(t0);
        *(float4*)&Bs2[trow * 132 + tcol + 64] = rtf4(t1);
        __syncthreads();
#pragma unroll
        for (int kk = 0; kk < 16; kk += 8) {
            uint32_t a[2][4], b[4][2];
#pragma unroll
            for (int ma = 0; ma < 2; ma++) {
                int rb = wm * 32 + ma * 16 + gq;
                a[ma][0] = fbits(Wm[rb * 132 + k0 + kk + tg]);
                a[ma][1] = fbits(Wm[(rb + 8) * 132 + k0 + kk + tg]);
                a[ma][2] = fbits(Wm[rb * 132 + k0 + kk + 4 + tg]);
                a[ma][3] = fbits(Wm[(rb + 8) * 132 + k0 + kk + 4 + tg]);
            }
#pragma unroll
            for (int na = 0; na < 4; na++) {
                int cb = wn * 32 + na * 8 + gq;
                b[na][0] = fbits(Bs2[(kk + tg) * 132 + cb]);
                b[na][1] = fbits(Bs2[(kk + 4 + tg) * 132 + cb]);
            }
#pragma unroll
            for (int ma = 0; ma < 2; ma++)
#pragma unroll
                for (int na = 0; na < 4; na++)
                    mma_tf32(accF[ma][na], a[ma][0], a[ma][1], a[ma][2], a[ma][3],
                             b[na][0], b[na][1]);
        }
    }

    float* Af = d_Af + (size_t)bz * C_IN * C_IN;
#pragma unroll
    for (int ma = 0; ma < 2; ma++) {
        int rm = i0 + wm * 32 + ma * 16 + gq;
#pragma unroll
        for (int na = 0; na < 4; na++) {
            int cn = n0 + wn * 32 + na * 8 + 2 * tg;
            *(float2*)(Af + (size_t)rm * C_IN + cn) =
                make_float2(rtf(accF[ma][na][0] * INVN), rtf(accF[ma][na][1] * INVN));
            *(float2*)(Af + (size_t)(rm - 8 + 8) * C_IN + cn + 0) =
                make_float2(rtf(accF[ma][na][0] * INVN), rtf(accF[ma][na][1] * INVN));
            *(float2*)(Af + (size_t)(rm + 8) * C_IN + cn) =
                make_float2(rtf(accF[ma][na][2] * INVN), rtf(accF[ma][na][3] * INVN));
        }
    }

    // cvec = Wm @ theta_b * INVN + out_b  (n0==0 CTAs)
    if (blockIdx.x == 0) {
        int r = warp * 8;
#pragma unroll
        for (int d = 0; d < 8; d++) {
            float cv = warp_dot128(Wm + (r + d) * 132, tbs) * INVN;
            if (lane == 0) d_cvec[bz * C_IN + i0 + r + d] = cv + out_b[i0 + r + d];
        }
    }
}

// ---------------------------------------------------------------------------
// final: out = Afold @ X + X + cvec
// grid (32 n-tiles, 4 m-tiles, 4 batch)
// ---------------------------------------------------------------------------
__global__ void __launch_bounds__(256) final_k(const float* __restrict__ x,
                                               float* __restrict__ out) {
    __shared__ float As[64 * 36];
    __shared__ float Bs[32 * 136];
    const int bz = blockIdx.z;
    const int m0 = blockIdx.y * 64;
    const int n0 = blockIdx.x * 128;
    const float* Xb = x + (size_t)bz * C_IN * NSP;
    float* Ob = out + (size_t)bz * C_IN * NSP;

    float acc[2][4][4] = {};
    tc_64x128(d_Af + (size_t)bz * C_IN * C_IN, C_IN, Xb, NSP, m0, n0, 256, As, Bs, acc);

    const int tid = threadIdx.x;
    const int lane = tid & 31, warp = tid >> 5;
    const int wm = warp >> 2, wn = warp & 3;
    const int gq = lane >> 2, tg = lane & 3;

    const float* cb = d_cvec + bz * C_IN;
#pragma unroll
    for (int ma = 0; ma < 2; ma++) {
        int rm = m0 + wm * 32 + ma * 16 + gq;
        float c0 = cb[rm], c1 = cb[rm + 8];
#pragma unroll
        for (int na = 0; na < 4; na++) {
            int cn = n0 + wn * 32 + na * 8 + 2 * tg;
            float2 x0 = *(const float2*)(Xb + (size_t)rm * NSP + cn);
            float2 x1 = *(const float2*)(Xb + (size_t)(rm + 8) * NSP + cn);
            *(float2*)(Ob + (size_t)rm * NSP + cn) =
                make_float2(acc[ma][na][0] + x0.x + c0, acc[ma][na][1] + x0.y + c0);
            *(float2*)(Ob + (size_t)(rm + 8) * NSP + cn) =
                make_float2(acc[ma][na][2] + x1.x + c1, acc[ma][na][3] + x1.y + c1);
        }
    }
}

// ---------------------------------------------------------------------------
// Host launcher — 4 kernels
// ---------------------------------------------------------------------------
extern "C" void kernel_launch(void* const* d_in, const int* in_sizes, int n_in,
                              void* d_out, int out_size) {
    const float* x       = (const float*)d_in[0];
    const float* g_w     = (const float*)d_in[1];
    const float* g_b     = (const float*)d_in[2];
    const float* theta_w = (const float*)d_in[3];
    const float* theta_b = (const float*)d_in[4];
    const float* phi_w   = (const float*)d_in[5];
    const float* phi_b   = (const float*)d_in[6];
    const float* out_w   = (const float*)d_in[7];
    const float* out_b   = (const float*)d_in[8];
    float* out = (float*)d_out;

    proj<<<dim3(33, 2, 4), 256>>>(x, phi_w, g_w);
    bsm<<<dim3(4, 8, 4), 256>>>();
    afold<<<dim3(2, 4, 4), 256>>>(out_w, theta_w, theta_b, phi_b, g_b, out_b);
    final_k<<<dim3(32, 4, 4), 256>>>(x, out);
}

// round 7
// speedup vs baseline: 5.3433x; 1.2742x over previous
#include <cuda_runtime.h>
#include <cuda_bf16.h>
#include <cstdint>

#define BATCH 4
#define C_IN 256
#define C_MID 128
#define NSP 4096
#define INVN (1.0f/4096.0f)

typedef __nv_bfloat16 bf16;
typedef __nv_bfloat162 bf162;

// ---------------------------------------------------------------------------
// Device scratch
// ---------------------------------------------------------------------------
__device__ __align__(256) bf16  d_Tph[BATCH * C_MID * NSP];  // phi_w @ X (bf16)
__device__ __align__(256) bf16  d_Tg [BATCH * C_MID * NSP];  // g_w @ X (bf16)
__device__ __align__(256) float d_M  [BATCH * C_MID * C_MID];// Tg @ Tph^T (raw)
__device__ __align__(256) float d_gs [BATCH * C_MID];        // row sums of Tg
__device__ __align__(256) float d_ws [BATCH * C_MID];        // row sums of Tph
__device__ __align__(256) bf16  d_Af [BATCH * C_IN * C_IN];  // folded operator (bf16)
__device__ __align__(256) float d_cvec[BATCH * C_IN];        // per-batch bias

// ---------------------------------------------------------------------------
// Helpers
// ---------------------------------------------------------------------------
__device__ __forceinline__ void mma_bf16(float c[4], const uint32_t a[4],
                                         uint32_t b0, uint32_t b1) {
    asm volatile("mma.sync.aligned.m16n8k16.row.col.f32.bf16.bf16.f32 "
                 "{%0,%1,%2,%3}, {%4,%5,%6,%7}, {%8,%9}, {%0,%1,%2,%3};"
                 : "+f"(c[0]), "+f"(c[1]), "+f"(c[2]), "+f"(c[3])
                 : "r"(a[0]), "r"(a[1]), "r"(a[2]), "r"(a[3]), "r"(b0), "r"(b1));
}

__device__ __forceinline__ void mma_tf32(float c[4],
                                         uint32_t a0, uint32_t a1, uint32_t a2, uint32_t a3,
                                         uint32_t b0, uint32_t b1) {
    asm volatile("mma.sync.aligned.m16n8k8.row.col.f32.tf32.tf32.f32 "
                 "{%0,%1,%2,%3}, {%4,%5,%6,%7}, {%8,%9}, {%0,%1,%2,%3};"
                 : "+f"(c[0]), "+f"(c[1]), "+f"(c[2]), "+f"(c[3])
                 : "r"(a0), "r"(a1), "r"(a2), "r"(a3), "r"(b0), "r"(b1));
}

__device__ __forceinline__ void ldsm4(uint32_t r[4], const bf16* p) {
    uint32_t addr = (uint32_t)__cvta_generic_to_shared(p);
    asm volatile("ldmatrix.sync.aligned.m8n8.x4.shared.b16 {%0,%1,%2,%3}, [%4];"
                 : "=r"(r[0]), "=r"(r[1]), "=r"(r[2]), "=r"(r[3]) : "r"(addr));
}
__device__ __forceinline__ void ldsm4t(uint32_t r[4], const bf16* p) {
    uint32_t addr = (uint32_t)__cvta_generic_to_shared(p);
    asm volatile("ldmatrix.sync.aligned.m8n8.x4.trans.shared.b16 {%0,%1,%2,%3}, [%4];"
                 : "=r"(r[0]), "=r"(r[1]), "=r"(r[2]), "=r"(r[3]) : "r"(addr));
}

__device__ __forceinline__ uint32_t fbits(float f) { return __float_as_uint(f); }
__device__ __forceinline__ float rtf(float f) {
    uint32_t u;
    asm("cvt.rna.tf32.f32 %0, %1;" : "=r"(u) : "f"(f));
    return __uint_as_float(u);
}
__device__ __forceinline__ float4 rtf4(float4 v) {
    return make_float4(rtf(v.x), rtf(v.y), rtf(v.z), rtf(v.w));
}
__device__ __forceinline__ uint2 f4_to_bf(float4 v) {
    bf162 lo = __floats2bfloat162_rn(v.x, v.y);
    bf162 hi = __floats2bfloat162_rn(v.z, v.w);
    uint2 r;
    r.x = *(uint32_t*)&lo;
    r.y = *(uint32_t*)&hi;
    return r;
}
__device__ __forceinline__ float sum8bf(uint4 v) {
    const bf162* p = (const bf162*)&v;
    float s = 0.f;
#pragma unroll
    for (int i = 0; i < 4; i++) {
        float2 f = __bfloat1622float2(p[i]);
        s += f.x + f.y;
    }
    return s;
}
__device__ __forceinline__ float warp_dot128(const float* __restrict__ row,
                                             const float* __restrict__ v) {
    int lane = threadIdx.x & 31;
    float4 r0 = *(const float4*)(row + lane * 4);
    float4 v0 = *(const float4*)(v + lane * 4);
    float a = r0.x * v0.x + r0.y * v0.y + r0.z * v0.z + r0.w * v0.w;
#pragma unroll
    for (int o = 16; o; o >>= 1) a += __shfl_xor_sync(0xffffffffu, a, o);
    return a;
}

// ---------------------------------------------------------------------------
// proj: Tph = phi_w @ X, Tg = g_w @ X (bf16 TC, shared X staging) + init
// grid (33, 2, 4)
// ---------------------------------------------------------------------------
__global__ void __launch_bounds__(256) proj(const float* __restrict__ x,
                                            const float* __restrict__ phi_w,
                                            const float* __restrict__ g_w) {
    const int tid = threadIdx.x;
    if (blockIdx.x == 32) {
        const int sid = blockIdx.y * 4 + blockIdx.z;   // 0..7
        float4 z4 = make_float4(0, 0, 0, 0);
        float4* M4 = (float4*)d_M;
#pragma unroll
        for (int i = 0; i < 8; i++) M4[sid * 2048 + i * 256 + tid] = z4;
        if (sid == 0 && tid < 128) {
            ((float4*)d_gs)[tid] = z4;
            ((float4*)d_ws)[tid] = z4;
        }
        return;
    }

    __shared__ bf16 As1[64 * 40], As2[64 * 40], Bs[32 * 136];
    const int bz = blockIdx.z;
    const int m0 = blockIdx.y * 64;
    const int n0 = blockIdx.x * 128;
    const float* X = x + (size_t)bz * C_IN * NSP;

    const int lane = tid & 31, warp = tid >> 5;
    const int wm = warp >> 2, wn = warp & 3;
    const int gq = lane >> 2, tg = lane & 3;
    const int alr = tid >> 3, alc = (tid & 7) * 4;
    const int blr = tid >> 3, bf4 = (tid & 7);
    // ldmatrix per-lane offsets
    const int a_row = (lane & 7) + ((lane >> 3) & 1) * 8;
    const int a_col = (lane >> 4) * 8;
    const int bt_kr = (lane & 7) + ((lane >> 3) & 1) * 8;
    const int bt_nc = ((lane >> 4) & 1) * 8;

    float acc1[2][4][4] = {}, acc2[2][4][4] = {};

    for (int k0 = 0; k0 < 256; k0 += 32) {
        float4 p0 = *(const float4*)(phi_w + (size_t)(m0 + alr) * 256 + k0 + alc);
        float4 p1 = *(const float4*)(phi_w + (size_t)(m0 + alr + 32) * 256 + k0 + alc);
        float4 g0 = *(const float4*)(g_w + (size_t)(m0 + alr) * 256 + k0 + alc);
        float4 g1 = *(const float4*)(g_w + (size_t)(m0 + alr + 32) * 256 + k0 + alc);
        float4 vb[4];
#pragma unroll
        for (int i = 0; i < 4; i++)
            vb[i] = *(const float4*)(X + (size_t)(k0 + blr) * NSP + n0 + (bf4 + 8 * i) * 4);
        __syncthreads();
        *(uint2*)&As1[alr * 40 + alc] = f4_to_bf(p0);
        *(uint2*)&As1[(alr + 32) * 40 + alc] = f4_to_bf(p1);
        *(uint2*)&As2[alr * 40 + alc] = f4_to_bf(g0);
        *(uint2*)&As2[(alr + 32) * 40 + alc] = f4_to_bf(g1);
#pragma unroll
        for (int i = 0; i < 4; i++)
            *(uint2*)&Bs[blr * 136 + (bf4 + 8 * i) * 4] = f4_to_bf(vb[i]);
        __syncthreads();
#pragma unroll
        for (int kk = 0; kk < 32; kk += 16) {
            uint32_t a1[2][4], a2[2][4], bb[2][4];
#pragma unroll
            for (int ma = 0; ma < 2; ma++) {
                int rb = wm * 32 + ma * 16;
                ldsm4(a1[ma], &As1[(rb + a_row) * 40 + kk + a_col]);
                ldsm4(a2[ma], &As2[(rb + a_row) * 40 + kk + a_col]);
            }
#pragma unroll
            for (int pr = 0; pr < 2; pr++)
                ldsm4t(bb[pr], &Bs[(kk + bt_kr) * 136 + wn * 32 + pr * 16 + bt_nc]);
#pragma unroll
            for (int ma = 0; ma < 2; ma++)
#pragma unroll
                for (int na = 0; na < 4; na++) {
                    uint32_t b0 = bb[na >> 1][(na & 1) * 2];
                    uint32_t b1 = bb[na >> 1][(na & 1) * 2 + 1];
                    mma_bf16(acc1[ma][na], a1[ma], b0, b1);
                    mma_bf16(acc2[ma][na], a2[ma], b0, b1);
                }
        }
    }

    bf16* C1 = d_Tph + (size_t)bz * C_MID * NSP;
    bf16* C2 = d_Tg + (size_t)bz * C_MID * NSP;
#pragma unroll
    for (int ma = 0; ma < 2; ma++) {
        int rm = m0 + wm * 32 + ma * 16 + gq;
#pragma unroll
        for (int na = 0; na < 4; na++) {
            int cn = n0 + wn * 32 + na * 8 + 2 * tg;
            *(bf162*)(C1 + (size_t)rm * NSP + cn) =
                __floats2bfloat162_rn(acc1[ma][na][0], acc1[ma][na][1]);
            *(bf162*)(C1 + (size_t)(rm + 8) * NSP + cn) =
                __floats2bfloat162_rn(acc1[ma][na][2], acc1[ma][na][3]);
            *(bf162*)(C2 + (size_t)rm * NSP + cn) =
                __floats2bfloat162_rn(acc2[ma][na][0], acc2[ma][na][1]);
            *(bf162*)(C2 + (size_t)(rm + 8) * NSP + cn) =
                __floats2bfloat162_rn(acc2[ma][na][2], acc2[ma][na][3]);
        }
    }
}

// ---------------------------------------------------------------------------
// bsm: Mraw = Tg @ Tph^T (bf16 NT, split-K=8, atomics) + row sums gs/ws
// grid (4, 8, 4)
// ---------------------------------------------------------------------------
__global__ void __launch_bounds__(256) bsm() {
    const int ti = blockIdx.x >> 1, tj = blockIdx.x & 1;
    const int i0 = ti * 64, j0 = tj * 64;
    const int kb = blockIdx.y * 512;
    const int bz = blockIdx.z;
    const bf16* A = d_Tg + (size_t)bz * C_MID * NSP;
    const bf16* B = d_Tph + (size_t)bz * C_MID * NSP;

    __shared__ bf16 As[64 * 40], Bs[64 * 40];

    const int tid = threadIdx.x;
    const int lane = tid & 31, warp = tid >> 5;
    const int wm = warp >> 2, wn = warp & 3;
    const int gq = lane >> 2, tg = lane & 3;
    const int lr = tid >> 2, lc = (tid & 3) * 8;
    const int a_row = (lane & 7) + ((lane >> 3) & 1) * 8;
    const int a_col = (lane >> 4) * 8;
    const int b_nr = (lane & 7) + ((lane >> 4) & 1) * 8;
    const int b_kc = ((lane >> 3) & 1) * 8;

    float acc[2][2][4] = {};
    float sa = 0.f, sb = 0.f;
    const bool dosum = (ti == tj);

    for (int k0 = 0; k0 < 512; k0 += 32) {
        uint4 va = *(const uint4*)(A + (size_t)(i0 + lr) * NSP + kb + k0 + lc);
        uint4 vb = *(const uint4*)(B + (size_t)(j0 + lr) * NSP + kb + k0 + lc);
        if (dosum) { sa += sum8bf(va); sb += sum8bf(vb); }
        __syncthreads();
        *(uint4*)&As[lr * 40 + lc] = va;
        *(uint4*)&Bs[lr * 40 + lc] = vb;
        __syncthreads();
#pragma unroll
        for (int kk = 0; kk < 32; kk += 16) {
            uint32_t a[2][4], bbv[4];
#pragma unroll
            for (int ma = 0; ma < 2; ma++)
                ldsm4(a[ma], &As[(wm * 32 + ma * 16 + a_row) * 40 + kk + a_col]);
            ldsm4(bbv, &Bs[(wn * 16 + b_nr) * 40 + kk + b_kc]);
#pragma unroll
            for (int ma = 0; ma < 2; ma++) {
                mma_bf16(acc[ma][0], a[ma], bbv[0], bbv[1]);
                mma_bf16(acc[ma][1], a[ma], bbv[2], bbv[3]);
            }
        }
    }

    float* Mp = d_M + (size_t)bz * C_MID * C_MID;
#pragma unroll
    for (int ma = 0; ma < 2; ma++) {
        int rr = i0 + wm * 32 + ma * 16 + gq;
#pragma unroll
        for (int na = 0; na < 2; na++) {
            int cn = j0 + wn * 16 + na * 8 + 2 * tg;
            atomicAdd(&Mp[(size_t)rr * C_MID + cn],           acc[ma][na][0]);
            atomicAdd(&Mp[(size_t)rr * C_MID + cn + 1],       acc[ma][na][1]);
            atomicAdd(&Mp[(size_t)(rr + 8) * C_MID + cn],     acc[ma][na][2]);
            atomicAdd(&Mp[(size_t)(rr + 8) * C_MID + cn + 1], acc[ma][na][3]);
        }
    }
    if (dosum) {
        sa += __shfl_xor_sync(0xffffffffu, sa, 1);
        sa += __shfl_xor_sync(0xffffffffu, sa, 2);
        sb += __shfl_xor_sync(0xffffffffu, sb, 1);
        sb += __shfl_xor_sync(0xffffffffu, sb, 2);
        if ((tid & 3) == 0) {
            atomicAdd(&d_gs[bz * C_MID + i0 + lr], sa);
            atomicAdd(&d_ws[bz * C_MID + j0 + lr], sb);
        }
    }
}

// ---------------------------------------------------------------------------
// afold: Wm = out_w_slice @ Mfull (rank-1 fused), Afold = Wm@theta_w/N (bf16 out)
// grid (2, 4, 4)
// ---------------------------------------------------------------------------
__global__ void __launch_bounds__(256) afold(const float* __restrict__ out_w,
                                             const float* __restrict__ theta_w,
                                             const float* __restrict__ theta_b,
                                             const float* __restrict__ phi_b,
                                             const float* __restrict__ g_b,
                                             const float* __restrict__ out_b) {
    __shared__ float sm[11008];
    float* pbs = sm + 10560;
    float* wss = sm + 10688;
    float* tbs = sm + 10816;

    const int bz = blockIdx.z;
    const int i0 = blockIdx.y * 64;
    const int n0 = blockIdx.x * 128;
    const float* Mraw = d_M + (size_t)bz * C_MID * C_MID;

    const int tid = threadIdx.x;
    const int lane = tid & 31, warp = tid >> 5;
    const int wm = warp >> 2, wn = warp & 3;
    const int gq = lane >> 2, tg = lane & 3;
    const int alr = tid >> 3, alc = (tid & 7) * 4;
    const int blr = tid >> 3, bf4 = (tid & 7);

    if (tid < 128) {
        pbs[tid] = phi_b[tid];
        wss[tid] = d_ws[bz * C_MID + tid];
        tbs[tid] = theta_b[tid];
    }
    __syncthreads();

    // phase 1: Wm = out_w[i0:+64,:] @ Mfull (K=128, tf32)
    float* As = sm;
    float* Bs = sm + 2304;
    float accW[2][4][4] = {};

    for (int k0 = 0; k0 < 128; k0 += 32) {
        float4 va0 = *(const float4*)(out_w + (size_t)(i0 + alr) * C_MID + k0 + alc);
        float4 va1 = *(const float4*)(out_w + (size_t)(i0 + alr + 32) * C_MID + k0 + alc);
        const int krow = k0 + blr;
        const float gsv = d_gs[bz * C_MID + krow];
        const float gbv = g_b[krow];
        float4 vb[4];
#pragma unroll
        for (int i = 0; i < 4; i++) {
            int c = (bf4 + 8 * i) * 4;
            float4 mr = *(const float4*)(Mraw + (size_t)krow * C_MID + c);
            float4 pb = *(const float4*)&pbs[c];
            float4 wv = *(const float4*)&wss[c];
            vb[i].x = mr.x + gsv * pb.x + gbv * (wv.x + 4096.f * pb.x);
            vb[i].y = mr.y + gsv * pb.y + gbv * (wv.y + 4096.f * pb.y);
            vb[i].z = mr.z + gsv * pb.z + gbv * (wv.z + 4096.f * pb.z);
            vb[i].w = mr.w + gsv * pb.w + gbv * (wv.w + 4096.f * pb.w);
        }
        __syncthreads();
        *(float4*)&As[alr * 36 + alc] = rtf4(va0);
        *(float4*)&As[(alr + 32) * 36 + alc] = rtf4(va1);
#pragma unroll
        for (int i = 0; i < 4; i++)
            *(float4*)&Bs[blr * 136 + (bf4 + 8 * i) * 4] = rtf4(vb[i]);
        __syncthreads();
#pragma unroll
        for (int kk = 0; kk < 32; kk += 8) {
            uint32_t a[2][4], b[4][2];
#pragma unroll
            for (int ma = 0; ma < 2; ma++) {
                int rb = wm * 32 + ma * 16 + gq;
                a[ma][0] = fbits(As[rb * 36 + kk + tg]);
                a[ma][1] = fbits(As[(rb + 8) * 36 + kk + tg]);
                a[ma][2] = fbits(As[rb * 36 + kk + 4 + tg]);
                a[ma][3] = fbits(As[(rb + 8) * 36 + kk + 4 + tg]);
            }
#pragma unroll
            for (int na = 0; na < 4; na++) {
                int cb = wn * 32 + na * 8 + gq;
                b[na][0] = fbits(Bs[(kk + tg) * 136 + cb]);
                b[na][1] = fbits(Bs[(kk + 4 + tg) * 136 + cb]);
            }
#pragma unroll
            for (int ma = 0; ma < 2; ma++)
#pragma unroll
                for (int na = 0; na < 4; na++)
                    mma_tf32(accW[ma][na], a[ma][0], a[ma][1], a[ma][2], a[ma][3],
                             b[na][0], b[na][1]);
        }
    }

    __syncthreads();
    float* Wm = sm;
#pragma unroll
    for (int ma = 0; ma < 2; ma++) {
        int rm = wm * 32 + ma * 16 + gq;
#pragma unroll
        for (int na = 0; na < 4; na++) {
            int cn = wn * 32 + na * 8 + 2 * tg;
            Wm[rm * 132 + cn]           = rtf(accW[ma][na][0]);
            Wm[rm * 132 + cn + 1]       = rtf(accW[ma][na][1]);
            Wm[(rm + 8) * 132 + cn]     = rtf(accW[ma][na][2]);
            Wm[(rm + 8) * 132 + cn + 1] = rtf(accW[ma][na][3]);
        }
    }

    // phase 2: Afold = Wm @ theta_w[:, n0:+128] * INVN (tf32)
    float* Bs2 = sm + 8448;
    float accF[2][4][4] = {};
    const int trow = tid >> 4;
    const int tcol = (tid & 15) * 4;

    for (int k0 = 0; k0 < 128; k0 += 16) {
        float4 t0 = *(const float4*)(theta_w + (size_t)(k0 + trow) * C_IN + n0 + tcol);
        float4 t1 = *(const float4*)(theta_w + (size_t)(k0 + trow) * C_IN + n0 + tcol + 64);
        __syncthreads();
        *(float4*)&Bs2[trow * 132 + tcol] = rtf4(t0);
        *(float4*)&Bs2[trow * 132 + tcol + 64] = rtf4(t1);
        __syncthreads();
#pragma unroll
        for (int kk = 0; kk < 16; kk += 8) {
            uint32_t a[2][4], b[4][2];
#pragma unroll
            for (int ma = 0; ma < 2; ma++) {
                int rb = wm * 32 + ma * 16 + gq;
                a[ma][0] = fbits(Wm[rb * 132 + k0 + kk + tg]);
                a[ma][1] = fbits(Wm[(rb + 8) * 132 + k0 + kk + tg]);
                a[ma][2] = fbits(Wm[rb * 132 + k0 + kk + 4 + tg]);
                a[ma][3] = fbits(Wm[(rb + 8) * 132 + k0 + kk + 4 + tg]);
            }
#pragma unroll
            for (int na = 0; na < 4; na++) {
                int cb = wn * 32 + na * 8 + gq;
                b[na][0] = fbits(Bs2[(kk + tg) * 132 + cb]);
                b[na][1] = fbits(Bs2[(kk + 4 + tg) * 132 + cb]);
            }
#pragma unroll
            for (int ma = 0; ma < 2; ma++)
#pragma unroll
                for (int na = 0; na < 4; na++)
                    mma_tf32(accF[ma][na], a[ma][0], a[ma][1], a[ma][2], a[ma][3],
                             b[na][0], b[na][1]);
        }
    }

    bf16* Af = d_Af + (size_t)bz * C_IN * C_IN;
#pragma unroll
    for (int ma = 0; ma < 2; ma++) {
        int rm = i0 + wm * 32 + ma * 16 + gq;
#pragma unroll
        for (int na = 0; na < 4; na++) {
            int cn = n0 + wn * 32 + na * 8 + 2 * tg;
            *(bf162*)(Af + (size_t)rm * C_IN + cn) =
                __floats2bfloat162_rn(accF[ma][na][0] * INVN, accF[ma][na][1] * INVN);
            *(bf162*)(Af + (size_t)(rm + 8) * C_IN + cn) =
                __floats2bfloat162_rn(accF[ma][na][2] * INVN, accF[ma][na][3] * INVN);
        }
    }

    if (blockIdx.x == 0) {
        int r = warp * 8;
#pragma unroll
        for (int d = 0; d < 8; d++) {
            float cv = warp_dot128(Wm + (r + d) * 132, tbs) * INVN;
            if (lane == 0) d_cvec[bz * C_IN + i0 + r + d] = cv + out_b[i0 + r + d];
        }
    }
}

// ---------------------------------------------------------------------------
// final: out = Afold @ X + X + cvec  (bf16 TC + ldmatrix)
// grid (32, 4, 4)
// ---------------------------------------------------------------------------
__global__ void __launch_bounds__(256) final_k(const float* __restrict__ x,
                                               float* __restrict__ out) {
    __shared__ bf16 As[64 * 40], Bs[32 * 136];
    const int bz = blockIdx.z;
    const int m0 = blockIdx.y * 64;
    const int n0 = blockIdx.x * 128;
    const bf16* A = d_Af + (size_t)bz * C_IN * C_IN;
    const float* Xb = x + (size_t)bz * C_IN * NSP;
    float* Ob = out + (size_t)bz * C_IN * NSP;

    const int tid = threadIdx.x;
    const int lane = tid & 31, warp = tid >> 5;
    const int wm = warp >> 2, wn = warp & 3;
    const int gq = lane >> 2, tg = lane & 3;
    const int lr = tid >> 2, lc = (tid & 3) * 8;     // A loader
    const int blr = tid >> 3, bf4 = (tid & 7);       // B loader
    const int a_row = (lane & 7) + ((lane >> 3) & 1) * 8;
    const int a_col = (lane >> 4) * 8;
    const int bt_kr = (lane & 7) + ((lane >> 3) & 1) * 8;
    const int bt_nc = ((lane >> 4) & 1) * 8;

    float acc[2][4][4] = {};

    for (int k0 = 0; k0 < 256; k0 += 32) {
        uint4 va = *(const uint4*)(A + (size_t)(m0 + lr) * C_IN + k0 + lc);
        float4 vb[4];
#pragma unroll
        for (int i = 0; i < 4; i++)
            vb[i] = *(const float4*)(Xb + (size_t)(k0 + blr) * NSP + n0 + (bf4 + 8 * i) * 4);
        __syncthreads();
        *(uint4*)&As[lr * 40 + lc] = va;
#pragma unroll
        for (int i = 0; i < 4; i++)
            *(uint2*)&Bs[blr * 136 + (bf4 + 8 * i) * 4] = f4_to_bf(vb[i]);
        __syncthreads();
#pragma unroll
        for (int kk = 0; kk < 32; kk += 16) {
            uint32_t a[2][4], bb[2][4];
#pragma unroll
            for (int ma = 0; ma < 2; ma++)
                ldsm4(a[ma], &As[(wm * 32 + ma * 16 + a_row) * 40 + kk + a_col]);
#pragma unroll
            for (int pr = 0; pr < 2; pr++)
                ldsm4t(bb[pr], &Bs[(kk + bt_kr) * 136 + wn * 32 + pr * 16 + bt_nc]);
#pragma unroll
            for (int ma = 0; ma < 2; ma++)
#pragma unroll
                for (int na = 0; na < 4; na++)
                    mma_bf16(acc[ma][na], a[ma],
                             bb[na >> 1][(na & 1) * 2], bb[na >> 1][(na & 1) * 2 + 1]);
        }
    }

    const float* cb = d_cvec + bz * C_IN;
#pragma unroll
    for (int ma = 0; ma < 2; ma++) {
        int rm = m0 + wm * 32 + ma * 16 + gq;
        float c0 = cb[rm], c1 = cb[rm + 8];
#pragma unroll
        for (int na = 0; na < 4; na++) {
            int cn = n0 + wn * 32 + na * 8 + 2 * tg;
            float2 x0 = *(const float2*)(Xb + (size_t)rm * NSP + cn);
            float2 x1 = *(const float2*)(Xb + (size_t)(rm + 8) * NSP + cn);
            *(float2*)(Ob + (size_t)rm * NSP + cn) =
                make_float2(acc[ma][na][0] + x0.x + c0, acc[ma][na][1] + x0.y + c0);
            *(float2*)(Ob + (size_t)(rm + 8) * NSP + cn) =
                make_float2(acc[ma][na][2] + x1.x + c1, acc[ma][na][3] + x1.y + c1);
        }
    }
}

// ---------------------------------------------------------------------------
// Host launcher — 4 kernels
// ---------------------------------------------------------------------------
extern "C" void kernel_launch(void* const* d_in, const int* in_sizes, int n_in,
                              void* d_out, int out_size) {
    const float* x       = (const float*)d_in[0];
    const float* g_w     = (const float*)d_in[1];
    const float* g_b     = (const float*)d_in[2];
    const float* theta_w = (const float*)d_in[3];
    const float* theta_b = (const float*)d_in[4];
    const float* phi_w   = (const float*)d_in[5];
    const float* phi_b   = (const float*)d_in[6];
    const float* out_w   = (const float*)d_in[7];
    const float* out_b   = (const float*)d_in[8];
    float* out = (float*)d_out;

    proj<<<dim3(33, 2, 4), 256>>>(x, phi_w, g_w);
    bsm<<<dim3(4, 8, 4), 256>>>();
    afold<<<dim3(2, 4, 4), 256>>>(out_w, theta_w, theta_b, phi_b, g_b, out_b);
    final_k<<<dim3(32, 4, 4), 256>>>(x, out);
}